// round 3
// baseline (speedup 1.0000x reference)
#include <cuda_runtime.h>
#include <math.h>
#include <stdint.h>

#define B_SZ 8192
#define T_SZ 8192
#define FD 768
#define PD 512
#define HD 1024
#define NE 4
#define CB 1024  // 2*P

// ---------------- scratch (device globals; no allocation allowed) ----------
__device__ float g_comb[(size_t)B_SZ * CB];          // 32 MB
__device__ float g_rth[(size_t)B_SZ * 256];          // 8 MB
__device__ float g_probs[(size_t)B_SZ * NE];
__device__ float g_expert[(size_t)B_SZ * NE * HD];   // 128 MB
__device__ float g_dsh[(size_t)B_SZ * HD];           // 32 MB
__device__ float g_ds[B_SZ];
__device__ float g_fused[(size_t)B_SZ * HD];         // 32 MB
__device__ float g_res[(size_t)B_SZ * FD];           // 24 MB
__device__ float g_pred[(size_t)B_SZ * FD];          // 24 MB
__device__ float g_tgt[(size_t)T_SZ * FD];           // 24 MB

// ---------------- helpers ---------------------------------------------------
__device__ __forceinline__ float gelu_f(float x) {
    return 0.5f * x * (1.0f + erff(x * 0.70710678118654752440f));
}

// Blackwell packed fp32x2 FMA (2 FMAs per instruction; ptxas won't emit from C++)
__device__ __forceinline__ float2 ffma2(float2 a, float2 b, float2 c) {
    float2 d;
    asm("fma.rn.f32x2 %0, %1, %2, %3;"
        : "=l"(reinterpret_cast<unsigned long long&>(d))
        : "l"(reinterpret_cast<unsigned long long&>(a)),
          "l"(reinterpret_cast<unsigned long long&>(b)),
          "l"(reinterpret_cast<unsigned long long&>(c)));
    return d;
}

// ---------------- generic NT SGEMM: C = act(A[M,K] @ W[N,K]^T + bias) * scale
// A row-major lda=K, W row-major ldw=K, C row-major with ldc.
// Tiles: 128x128x16, 256 threads, 8x8 per thread (as 8x4 float2 accumulators).
// All M,N multiples of 128; K multiple of 16 (true for every call here).
__global__ void __launch_bounds__(256, 2)
gemm_nt(const float* __restrict__ A, const float* __restrict__ W,
        const float* __restrict__ bias, float* __restrict__ C,
        int K, int ldc, int act, const float* __restrict__ scale_ptr)
{
    __shared__ float As[16][128];
    __shared__ float Bs[16][128];

    const int t  = threadIdx.x;
    const int tx = t & 15;   // 16 col groups
    const int ty = t >> 4;   // 16 row groups

    const float* Ab = A + (size_t)blockIdx.y * 128 * K;
    const float* Wb = W + (size_t)blockIdx.x * 128 * K;

    float2 acc[8][4];
#pragma unroll
    for (int i = 0; i < 8; i++)
#pragma unroll
        for (int j = 0; j < 4; j++) acc[i][j] = make_float2(0.f, 0.f);

    for (int k0 = 0; k0 < K; k0 += 16) {
#pragma unroll
        for (int i = 0; i < 2; i++) {
            int idx = t + i * 256;
            int r = idx >> 2;          // 0..127
            int c = (idx & 3) << 2;    // 0,4,8,12
            float4 va = *(const float4*)(Ab + (size_t)r * K + k0 + c);
            As[c + 0][r] = va.x; As[c + 1][r] = va.y;
            As[c + 2][r] = va.z; As[c + 3][r] = va.w;
            float4 vb = *(const float4*)(Wb + (size_t)r * K + k0 + c);
            Bs[c + 0][r] = vb.x; Bs[c + 1][r] = vb.y;
            Bs[c + 2][r] = vb.z; Bs[c + 3][r] = vb.w;
        }
        __syncthreads();
#pragma unroll
        for (int k = 0; k < 16; k++) {
            float4 a0 = *(const float4*)&As[k][ty * 8];
            float4 a1 = *(const float4*)&As[k][ty * 8 + 4];
            float4 b0 = *(const float4*)&Bs[k][tx * 8];
            float4 b1 = *(const float4*)&Bs[k][tx * 8 + 4];
            float  av[8] = {a0.x, a0.y, a0.z, a0.w, a1.x, a1.y, a1.z, a1.w};
            float2 bv[4] = {make_float2(b0.x, b0.y), make_float2(b0.z, b0.w),
                            make_float2(b1.x, b1.y), make_float2(b1.z, b1.w)};
#pragma unroll
            for (int i = 0; i < 8; i++) {
                float2 ad = make_float2(av[i], av[i]);
#pragma unroll
                for (int j = 0; j < 4; j++) acc[i][j] = ffma2(ad, bv[j], acc[i][j]);
            }
        }
        __syncthreads();
    }

    float scale = scale_ptr ? expf(scale_ptr[0]) : 1.0f;
    const int mbase = blockIdx.y * 128 + ty * 8;
    const int nbase = blockIdx.x * 128 + tx * 8;
#pragma unroll
    for (int i = 0; i < 8; i++) {
        float* Crow = C + (size_t)(mbase + i) * ldc + nbase;
#pragma unroll
        for (int j = 0; j < 4; j++) {
            float x0 = acc[i][j].x, x1 = acc[i][j].y;
            int n = nbase + j * 2;
            if (bias) { x0 += bias[n]; x1 += bias[n + 1]; }
            if (act)  { x0 = gelu_f(x0); x1 = gelu_f(x1); }
            *(float2*)(Crow + j * 2) = make_float2(x0 * scale, x1 * scale);
        }
    }
}

// ---------------- router: logits (4 x 256-dot) + softmax --------------------
__global__ void router_kernel(const float* __restrict__ rth,
                              const float* __restrict__ W2,
                              const float* __restrict__ b2,
                              float* __restrict__ probs_buf,
                              float* __restrict__ out_probs)
{
    int b = blockIdx.x;
    int lane = threadIdx.x & 31;
    int w = threadIdx.x >> 5;  // expert id 0..3
    const float* x = rth + (size_t)b * 256;
    const float* wr = W2 + (size_t)w * 256;
    float s = 0.f;
    for (int i = lane; i < 256; i += 32) s += x[i] * wr[i];
#pragma unroll
    for (int o = 16; o; o >>= 1) s += __shfl_xor_sync(0xffffffffu, s, o);
    __shared__ float sl[4];
    if (lane == 0) sl[w] = s + b2[w];
    __syncthreads();
    if (threadIdx.x == 0) {
        float m = fmaxf(fmaxf(sl[0], sl[1]), fmaxf(sl[2], sl[3]));
        float e[4]; float sum = 0.f;
#pragma unroll
        for (int i = 0; i < 4; i++) { e[i] = expf(sl[i] - m); sum += e[i]; }
        float inv = 1.f / sum;
#pragma unroll
        for (int i = 0; i < 4; i++) {
            float p = e[i] * inv;
            probs_buf[(size_t)b * 4 + i] = p;
            out_probs[(size_t)b * 4 + i] = p;
        }
    }
}

// ---------------- ds scalar + MoE mix ---------------------------------------
__global__ void fuse_kernel(const float* __restrict__ dsh,
                            const float* __restrict__ dsW2,
                            const float* __restrict__ dsb2,
                            const float* __restrict__ expert,
                            const float* __restrict__ probs,
                            float* __restrict__ fused,
                            float* __restrict__ ds_buf,
                            float* __restrict__ out_ds)
{
    int b = blockIdx.x;
    int t = threadIdx.x;  // 256
    const float* xr = dsh + (size_t)b * HD;
    float s = 0.f;
    for (int k = t; k < HD; k += 256) s += xr[k] * dsW2[k];
    __shared__ float red[256];
    red[t] = s;
    __syncthreads();
    for (int off = 128; off; off >>= 1) {
        if (t < off) red[t] += red[t + off];
        __syncthreads();
    }
    if (t == 0) {
        float d = 1.f / (1.f + expf(-(red[0] + dsb2[0])));
        ds_buf[b] = d;
        out_ds[b] = d;
    }
    float p0 = probs[(size_t)b * 4 + 0], p1 = probs[(size_t)b * 4 + 1];
    float p2 = probs[(size_t)b * 4 + 2], p3 = probs[(size_t)b * 4 + 3];
    const float* eb = expert + (size_t)b * (NE * HD);
    for (int h = t; h < HD; h += 256)
        fused[(size_t)b * HD + h] =
            p0 * eb[h] + p1 * eb[HD + h] + p2 * eb[2 * HD + h] + p3 * eb[3 * HD + h];
}

// ---------------- mix + L2 normalize (pred rows and target rows) ------------
__global__ void norm_kernel(const float* __restrict__ res,
                            const float* __restrict__ text,
                            const float* __restrict__ img,
                            const float* __restrict__ ds_buf,
                            const float* __restrict__ target,
                            float* __restrict__ pred,
                            float* __restrict__ tgtn)
{
    int r = blockIdx.x;
    int t = threadIdx.x;  // 256, row length 768 = 3*256
    float o[3];
    float* dst;
    if (r < B_SZ) {
        float d = ds_buf[r];
        const size_t base = (size_t)r * FD;
#pragma unroll
        for (int i = 0; i < 3; i++) {
            int j = t + i * 256;
            o[i] = d * text[base + j] + (1.0f - d) * img[base + j] + res[base + j];
        }
        dst = pred + base;
    } else {
        const size_t base = (size_t)(r - B_SZ) * FD;
#pragma unroll
        for (int i = 0; i < 3; i++) o[i] = target[base + t + i * 256];
        dst = tgtn + base;
    }
    float s = o[0] * o[0] + o[1] * o[1] + o[2] * o[2];
    __shared__ float red[256];
    red[t] = s;
    __syncthreads();
    for (int off = 128; off; off >>= 1) {
        if (t < off) red[t] += red[t + off];
        __syncthreads();
    }
    __shared__ float inv_s;
    if (t == 0) inv_s = 1.0f / fmaxf(sqrtf(red[0]), 1e-12f);
    __syncthreads();
    float inv = inv_s;
#pragma unroll
    for (int i = 0; i < 3; i++) dst[t + i * 256] = o[i] * inv;
}

// ---------------- launch -----------------------------------------------------
extern "C" void kernel_launch(void* const* d_in, const int* in_sizes, int n_in,
                              void* d_out, int out_size)
{
    const float* img  = (const float*)d_in[0];
    const float* txt  = (const float*)d_in[1];
    const float* tgt  = (const float*)d_in[2];
    const float* Wt   = (const float*)d_in[3];
    const float* bt   = (const float*)d_in[4];
    const float* Wi   = (const float*)d_in[5];
    const float* bi   = (const float*)d_in[6];
    const float* dsW1 = (const float*)d_in[7];
    const float* dsb1 = (const float*)d_in[8];
    const float* dsW2 = (const float*)d_in[9];
    const float* dsb2 = (const float*)d_in[10];
    const float* expW = (const float*)d_in[11];
    const float* expb = (const float*)d_in[12];
    const float* rtW1 = (const float*)d_in[13];
    const float* rtb1 = (const float*)d_in[14];
    const float* rtW2 = (const float*)d_in[15];
    const float* rtb2 = (const float*)d_in[16];
    const float* outW = (const float*)d_in[17];
    const float* outb = (const float*)d_in[18];
    const float* lsc  = (const float*)d_in[19];

    float *comb, *rth, *probs, *expert, *dsh, *ds, *fused, *res, *pred, *tgtn;
    cudaGetSymbolAddress((void**)&comb,   g_comb);
    cudaGetSymbolAddress((void**)&rth,    g_rth);
    cudaGetSymbolAddress((void**)&probs,  g_probs);
    cudaGetSymbolAddress((void**)&expert, g_expert);
    cudaGetSymbolAddress((void**)&dsh,    g_dsh);
    cudaGetSymbolAddress((void**)&ds,     g_ds);
    cudaGetSymbolAddress((void**)&fused,  g_fused);
    cudaGetSymbolAddress((void**)&res,    g_res);
    cudaGetSymbolAddress((void**)&pred,   g_pred);
    cudaGetSymbolAddress((void**)&tgtn,   g_tgt);

    float* out_logits = (float*)d_out;
    float* out_ds     = out_logits + (size_t)B_SZ * T_SZ;
    float* out_probs  = out_ds + B_SZ;

    dim3 blk(256);

    // projections -> comb [B, 1024]  (text -> cols 0:512, image -> cols 512:1024)
    gemm_nt<<<dim3(PD / 128, B_SZ / 128), blk>>>(txt, Wt, bt, comb,      FD, CB, 1, nullptr);
    gemm_nt<<<dim3(PD / 128, B_SZ / 128), blk>>>(img, Wi, bi, comb + PD, FD, CB, 1, nullptr);

    // router hidden [B,256], then logits+softmax
    gemm_nt<<<dim3(256 / 128, B_SZ / 128), blk>>>(comb, rtW1, rtb1, rth, CB, 256, 1, nullptr);
    router_kernel<<<B_SZ, 128>>>(rth, rtW2, rtb2, probs, out_probs);

    // experts as one fused GEMM: [B, 4096] = gelu(comb @ expW_flat^T + expb_flat)
    gemm_nt<<<dim3((NE * HD) / 128, B_SZ / 128), blk>>>(comb, expW, expb, expert, CB, NE * HD, 1, nullptr);

    // ds hidden [B, 1024]
    gemm_nt<<<dim3(HD / 128, B_SZ / 128), blk>>>(comb, dsW1, dsb1, dsh, CB, HD, 1, nullptr);

    // ds scalar + router-weighted expert mix
    fuse_kernel<<<B_SZ, 256>>>(dsh, dsW2, dsb2, expert, probs, fused, ds, out_ds);

    // residual [B, 768]
    gemm_nt<<<dim3(FD / 128, B_SZ / 128), blk>>>(fused, outW, outb, res, HD, FD, 0, nullptr);

    // mix + normalize (pred rows, then target rows)
    norm_kernel<<<B_SZ + T_SZ, 256>>>(res, txt, img, ds, tgt, pred, tgtn);

    // logits = exp(logit_scale) * pred @ tgtn^T   [8192, 8192]
    gemm_nt<<<dim3(T_SZ / 128, B_SZ / 128), blk>>>(pred, tgtn, nullptr, out_logits, FD, T_SZ, 0, lsc);
}

// round 5
// speedup vs baseline: 2.9517x; 2.9517x over previous
#include <cuda_runtime.h>
#include <cuda_bf16.h>
#include <math.h>
#include <stdint.h>

#define B_SZ 8192
#define T_SZ 8192
#define FD 768
#define PD 512
#define HD 1024
#define NE 4
#define CB 1024  // 2*P

typedef __nv_bfloat16 bf16;

// ---------------- scratch (device globals; no allocation allowed) ----------
__device__ float g_rth[(size_t)B_SZ * 256];
__device__ float g_probs[(size_t)B_SZ * NE];
__device__ float g_expert[(size_t)B_SZ * NE * HD];
__device__ float g_dsh[(size_t)B_SZ * HD];
__device__ float g_ds[B_SZ];
__device__ float g_res[(size_t)B_SZ * FD];

__device__ __align__(256) bf16 g_txt_h[(size_t)B_SZ * FD];
__device__ __align__(256) bf16 g_txt_l[(size_t)B_SZ * FD];
__device__ __align__(256) bf16 g_img_h[(size_t)B_SZ * FD];
__device__ __align__(256) bf16 g_img_l[(size_t)B_SZ * FD];
__device__ __align__(256) bf16 g_comb_h[(size_t)B_SZ * CB];
__device__ __align__(256) bf16 g_comb_l[(size_t)B_SZ * CB];
__device__ __align__(256) bf16 g_fused_h[(size_t)B_SZ * HD];
__device__ __align__(256) bf16 g_fused_l[(size_t)B_SZ * HD];
__device__ __align__(256) bf16 g_pred_h[(size_t)B_SZ * FD];
__device__ __align__(256) bf16 g_pred_l[(size_t)B_SZ * FD];
__device__ __align__(256) bf16 g_tgt_h[(size_t)T_SZ * FD];
__device__ __align__(256) bf16 g_tgt_l[(size_t)T_SZ * FD];
__device__ __align__(256) bf16 g_Wt_h[(size_t)PD * FD];
__device__ __align__(256) bf16 g_Wt_l[(size_t)PD * FD];
__device__ __align__(256) bf16 g_Wi_h[(size_t)PD * FD];
__device__ __align__(256) bf16 g_Wi_l[(size_t)PD * FD];
__device__ __align__(256) bf16 g_rtW1_h[(size_t)256 * CB];
__device__ __align__(256) bf16 g_rtW1_l[(size_t)256 * CB];
__device__ __align__(256) bf16 g_expW_h[(size_t)NE * HD * CB];
__device__ __align__(256) bf16 g_expW_l[(size_t)NE * HD * CB];
__device__ __align__(256) bf16 g_dsW1_h[(size_t)HD * CB];
__device__ __align__(256) bf16 g_dsW1_l[(size_t)HD * CB];
__device__ __align__(256) bf16 g_outW_h[(size_t)FD * HD];
__device__ __align__(256) bf16 g_outW_l[(size_t)FD * HD];

// ---------------- helpers ---------------------------------------------------
__device__ __forceinline__ float gelu_f(float x) {
    return 0.5f * x * (1.0f + erff(x * 0.70710678118654752440f));
}

__device__ __forceinline__ uint32_t smem_u32(const void* p) {
    uint32_t a;
    asm("{ .reg .u64 t; cvta.to.shared.u64 t, %1; cvt.u32.u64 %0, t; }" : "=r"(a) : "l"(p));
    return a;
}

__device__ __forceinline__ void cpasync16(uint32_t dst, const void* src) {
    asm volatile("cp.async.cg.shared.global [%0], [%1], 16;" :: "r"(dst), "l"(src));
}
__device__ __forceinline__ void cp_commit() {
    asm volatile("cp.async.commit_group;" ::: "memory");
}
__device__ __forceinline__ void cp_wait1() {
    asm volatile("cp.async.wait_group 1;" ::: "memory");
}
__device__ __forceinline__ void cp_wait0() {
    asm volatile("cp.async.wait_group 0;" ::: "memory");
}

__device__ __forceinline__ void ldsm4(uint32_t& r0, uint32_t& r1, uint32_t& r2, uint32_t& r3,
                                      uint32_t a) {
    asm volatile("ldmatrix.sync.aligned.m8n8.x4.shared.b16 {%0,%1,%2,%3}, [%4];"
                 : "=r"(r0), "=r"(r1), "=r"(r2), "=r"(r3) : "r"(a));
}

__device__ __forceinline__ void mma16816(float* c, const uint32_t* a, uint32_t b0, uint32_t b1) {
    asm volatile(
        "mma.sync.aligned.m16n8k16.row.col.f32.bf16.bf16.f32 "
        "{%0,%1,%2,%3}, {%4,%5,%6,%7}, {%8,%9}, {%0,%1,%2,%3};"
        : "+f"(c[0]), "+f"(c[1]), "+f"(c[2]), "+f"(c[3])
        : "r"(a[0]), "r"(a[1]), "r"(a[2]), "r"(a[3]), "r"(b0), "r"(b1));
}

// ---------------- split: f32 -> (hi, lo) bf16 --------------------------------
__global__ void split_kernel(const float* __restrict__ x,
                             bf16* __restrict__ h, bf16* __restrict__ l)
{
    size_t i = (size_t)blockIdx.x * 256 + threadIdx.x;
    float v = x[i];
    bf16 hh = __float2bfloat16(v);
    h[i] = hh;
    l[i] = __float2bfloat16(v - __bfloat162float(hh));
}

// ---------------- split-bf16 HMMA GEMM ---------------------------------------
// C[M,N] = act( (Ah+Al)[M,K] @ (Bh+Bl)[N,K]^T + bias ) * scale
// CTA tile 128x256, K-step 64, 8 warps (64x64 warp tiles), 2-stage cp.async.
// smem per stage: Ah 16K @0, Al 16K @16384, Bh 32K @32768, Bl 32K @65536.
#define STAGE_BYTES 98304
#define SMEM_GEMM (2 * STAGE_BYTES)

__device__ __forceinline__ void load_stage(
    uint32_t sb,
    const bf16* __restrict__ Ah, const bf16* __restrict__ Al,
    const bf16* __restrict__ Bh, const bf16* __restrict__ Bl,
    int m0, int n0, int k0, int K, int t)
{
#pragma unroll
    for (int i = 0; i < 4; i++) {          // A: 128 rows x 8 chunks = 1024
        int id = t + (i << 8);
        int row = id >> 3, ch = id & 7;
        uint32_t off = (uint32_t)(row << 7) + (uint32_t)((ch ^ (row & 7)) << 4);
        size_t g = (size_t)(m0 + row) * K + k0 + (ch << 3);
        cpasync16(sb + off, Ah + g);
        cpasync16(sb + 16384 + off, Al + g);
    }
#pragma unroll
    for (int i = 0; i < 8; i++) {          // B: 256 rows x 8 chunks = 2048
        int id = t + (i << 8);
        int row = id >> 3, ch = id & 7;
        uint32_t off = (uint32_t)(row << 7) + (uint32_t)((ch ^ (row & 7)) << 4);
        size_t g = (size_t)(n0 + row) * K + k0 + (ch << 3);
        cpasync16(sb + 32768 + off, Bh + g);
        cpasync16(sb + 65536 + off, Bl + g);
    }
}

#define MMA_ALL(Aset, Bset)                                            \
    do {                                                               \
        _Pragma("unroll")                                              \
        for (int mi = 0; mi < 4; mi++) {                               \
            _Pragma("unroll")                                          \
            for (int nj = 0; nj < 4; nj++) {                           \
                mma16816(acc[mi][nj * 2],     Aset[mi], Bset[nj][0], Bset[nj][1]); \
                mma16816(acc[mi][nj * 2 + 1], Aset[mi], Bset[nj][2], Bset[nj][3]); \
            }                                                          \
        }                                                              \
    } while (0)

__global__ void __launch_bounds__(256, 1)
gemm_tc(const bf16* __restrict__ Ah, const bf16* __restrict__ Al,
        const bf16* __restrict__ Bh, const bf16* __restrict__ Bl,
        const float* __restrict__ bias,
        float* __restrict__ Cf, bf16* __restrict__ Chi, bf16* __restrict__ Clo,
        int K, int ldc, int act, const float* __restrict__ scale_ptr)
{
    extern __shared__ __align__(128) char smem[];
    const uint32_t sb = smem_u32(smem);
    const int t = threadIdx.x;
    const int lane = t & 31, wid = t >> 5;
    const int wm = wid >> 2, wn = wid & 3;       // 2 x 4 warp grid
    const int m0 = blockIdx.y * 128;
    const int n0 = blockIdx.x * 256;

    float acc[4][8][4];
#pragma unroll
    for (int i = 0; i < 4; i++)
#pragma unroll
        for (int j = 0; j < 8; j++)
#pragma unroll
            for (int q = 0; q < 4; q++) acc[i][j][q] = 0.f;

    // per-lane ldmatrix address components (matrix id m = lane>>3, r = lane&7)
    const int lm = lane >> 3, lr8 = lane & 7;
    const int a_rowoff = ((lm & 1) << 3) + lr8;  // A: m0,m2 -> +0 ; m1,m3 -> +8
    const int a_choff  = (lm >> 1);              // A: m0,m1 -> k-chunk 0 ; m2,m3 -> 1
    const int b_rowoff = ((lm >> 1) << 3) + lr8; // B: m0,m1 -> +0 ; m2,m3 -> +8
    const int b_choff  = (lm & 1);               // B: m0,m2 -> 0 ; m1,m3 -> 1

    const int iters = K >> 6;
    load_stage(sb, Ah, Al, Bh, Bl, m0, n0, 0, K, t);
    cp_commit();

    for (int kt = 0; kt < iters; kt++) {
        const int s = kt & 1;
        if (kt + 1 < iters) {
            load_stage(sb + (s ^ 1) * STAGE_BYTES, Ah, Al, Bh, Bl, m0, n0, (kt + 1) << 6, K, t);
            cp_commit();
            cp_wait1();
        } else {
            cp_wait0();
        }
        __syncthreads();

        const uint32_t ss = sb + s * STAGE_BYTES;
#pragma unroll 1
        for (int kk = 0; kk < 4; kk++) {
            uint32_t Ahf[4][4], Bhf[4][4], Alf[4][4], Blf[4][4];
            const int chA = 2 * kk + a_choff;
            const int chB = 2 * kk + b_choff;
#pragma unroll
            for (int mi = 0; mi < 4; mi++) {
                int row = wm * 64 + mi * 16 + a_rowoff;
                uint32_t ad = ss + (row << 7) + (((chA ^ (row & 7))) << 4);
                ldsm4(Ahf[mi][0], Ahf[mi][1], Ahf[mi][2], Ahf[mi][3], ad);
            }
#pragma unroll
            for (int nj = 0; nj < 4; nj++) {
                int row = wn * 64 + nj * 16 + b_rowoff;
                uint32_t ad = ss + 32768 + (row << 7) + (((chB ^ (row & 7))) << 4);
                ldsm4(Bhf[nj][0], Bhf[nj][1], Bhf[nj][2], Bhf[nj][3], ad);
            }
            MMA_ALL(Ahf, Bhf);                       // Ah * Bh
#pragma unroll
            for (int nj = 0; nj < 4; nj++) {
                int row = wn * 64 + nj * 16 + b_rowoff;
                uint32_t ad = ss + 65536 + (row << 7) + (((chB ^ (row & 7))) << 4);
                ldsm4(Blf[nj][0], Blf[nj][1], Blf[nj][2], Blf[nj][3], ad);
            }
            MMA_ALL(Ahf, Blf);                       // Ah * Bl
#pragma unroll
            for (int mi = 0; mi < 4; mi++) {
                int row = wm * 64 + mi * 16 + a_rowoff;
                uint32_t ad = ss + 16384 + (row << 7) + (((chA ^ (row & 7))) << 4);
                ldsm4(Alf[mi][0], Alf[mi][1], Alf[mi][2], Alf[mi][3], ad);
            }
            MMA_ALL(Alf, Bhf);                       // Al * Bh
        }
        __syncthreads();
    }

    // epilogue: direct stores from accumulators
    const float scale = scale_ptr ? expf(scale_ptr[0]) : 1.0f;
    const int lr = lane >> 2, lc = (lane & 3) * 2;
#pragma unroll
    for (int mi = 0; mi < 4; mi++) {
#pragma unroll
        for (int nj = 0; nj < 4; nj++) {
#pragma unroll
            for (int h = 0; h < 2; h++) {
                int col = n0 + wn * 64 + nj * 16 + h * 8 + lc;
                float bx = 0.f, by = 0.f;
                if (bias) { float2 bb = *(const float2*)(bias + col); bx = bb.x; by = bb.y; }
#pragma unroll
                for (int rh = 0; rh < 2; rh++) {
                    int row = m0 + wm * 64 + mi * 16 + rh * 8 + lr;
                    float v0 = acc[mi][nj * 2 + h][rh * 2 + 0] + bx;
                    float v1 = acc[mi][nj * 2 + h][rh * 2 + 1] + by;
                    if (act) { v0 = gelu_f(v0); v1 = gelu_f(v1); }
                    v0 *= scale; v1 *= scale;
                    size_t idx = (size_t)row * ldc + col;
                    if (Cf) *(float2*)(Cf + idx) = make_float2(v0, v1);
                    if (Chi) {
                        bf16 h0 = __float2bfloat16(v0);
                        bf16 h1 = __float2bfloat16(v1);
                        *(__nv_bfloat162*)(Chi + idx) = __nv_bfloat162(h0, h1);
                        *(__nv_bfloat162*)(Clo + idx) = __nv_bfloat162(
                            __float2bfloat16(v0 - __bfloat162float(h0)),
                            __float2bfloat16(v1 - __bfloat162float(h1)));
                    }
                }
            }
        }
    }
}

// ---------------- router: logits (4 x 256-dot) + softmax --------------------
__global__ void router_kernel(const float* __restrict__ rth,
                              const float* __restrict__ W2,
                              const float* __restrict__ b2,
                              float* __restrict__ probs_buf,
                              float* __restrict__ out_probs)
{
    int b = blockIdx.x;
    int lane = threadIdx.x & 31;
    int w = threadIdx.x >> 5;
    const float* x = rth + (size_t)b * 256;
    const float* wr = W2 + (size_t)w * 256;
    float s = 0.f;
    for (int i = lane; i < 256; i += 32) s += x[i] * wr[i];
#pragma unroll
    for (int o = 16; o; o >>= 1) s += __shfl_xor_sync(0xffffffffu, s, o);
    __shared__ float sl[4];
    if (lane == 0) sl[w] = s + b2[w];
    __syncthreads();
    if (threadIdx.x == 0) {
        float m = fmaxf(fmaxf(sl[0], sl[1]), fmaxf(sl[2], sl[3]));
        float e[4]; float sum = 0.f;
#pragma unroll
        for (int i = 0; i < 4; i++) { e[i] = expf(sl[i] - m); sum += e[i]; }
        float inv = 1.f / sum;
#pragma unroll
        for (int i = 0; i < 4; i++) {
            float p = e[i] * inv;
            probs_buf[(size_t)b * 4 + i] = p;
            out_probs[(size_t)b * 4 + i] = p;
        }
    }
}

// ---------------- ds scalar + MoE mix (emits fused as bf16 hi/lo) ------------
__global__ void fuse_kernel(const float* __restrict__ dsh,
                            const float* __restrict__ dsW2,
                            const float* __restrict__ dsb2,
                            const float* __restrict__ expert,
                            const float* __restrict__ probs,
                            bf16* __restrict__ fusedh, bf16* __restrict__ fusedl,
                            float* __restrict__ ds_buf,
                            float* __restrict__ out_ds)
{
    int b = blockIdx.x;
    int t = threadIdx.x;  // 256
    const float* xr = dsh + (size_t)b * HD;
    float s = 0.f;
    for (int k = t; k < HD; k += 256) s += xr[k] * dsW2[k];
    __shared__ float red[256];
    red[t] = s;
    __syncthreads();
    for (int off = 128; off; off >>= 1) {
        if (t < off) red[t] += red[t + off];
        __syncthreads();
    }
    if (t == 0) {
        float d = 1.f / (1.f + expf(-(red[0] + dsb2[0])));
        ds_buf[b] = d;
        out_ds[b] = d;
    }
    float p0 = probs[(size_t)b * 4 + 0], p1 = probs[(size_t)b * 4 + 1];
    float p2 = probs[(size_t)b * 4 + 2], p3 = probs[(size_t)b * 4 + 3];
    const float* eb = expert + (size_t)b * (NE * HD);
    for (int h = t; h < HD; h += 256) {
        float v = p0 * eb[h] + p1 * eb[HD + h] + p2 * eb[2 * HD + h] + p3 * eb[3 * HD + h];
        size_t i = (size_t)b * HD + h;
        bf16 hh = __float2bfloat16(v);
        fusedh[i] = hh;
        fusedl[i] = __float2bfloat16(v - __bfloat162float(hh));
    }
}

// ---------------- mix + L2 normalize, emit bf16 hi/lo ------------------------
__global__ void norm_kernel(const float* __restrict__ res,
                            const float* __restrict__ text,
                            const float* __restrict__ img,
                            const float* __restrict__ ds_buf,
                            const float* __restrict__ target,
                            bf16* __restrict__ predh, bf16* __restrict__ predl,
                            bf16* __restrict__ tgth,  bf16* __restrict__ tgtl)
{
    int r = blockIdx.x;
    int t = threadIdx.x;  // 256, row length 768 = 3*256
    float o[3];
    bf16 *dh, *dl;
    size_t base;
    if (r < B_SZ) {
        float d = ds_buf[r];
        base = (size_t)r * FD;
#pragma unroll
        for (int i = 0; i < 3; i++) {
            int j = t + i * 256;
            o[i] = d * text[base + j] + (1.0f - d) * img[base + j] + res[base + j];
        }
        dh = predh; dl = predl;
    } else {
        base = (size_t)(r - B_SZ) * FD;
#pragma unroll
        for (int i = 0; i < 3; i++) o[i] = target[base + t + i * 256];
        dh = tgth; dl = tgtl;
    }
    float s = o[0] * o[0] + o[1] * o[1] + o[2] * o[2];
    __shared__ float red[256];
    red[t] = s;
    __syncthreads();
    for (int off = 128; off; off >>= 1) {
        if (t < off) red[t] += red[t + off];
        __syncthreads();
    }
    __shared__ float inv_s;
    if (t == 0) inv_s = 1.0f / fmaxf(sqrtf(red[0]), 1e-12f);
    __syncthreads();
    float inv = inv_s;
#pragma unroll
    for (int i = 0; i < 3; i++) {
        float v = o[i] * inv;
        bf16 hh = __float2bfloat16(v);
        size_t idx = base + t + i * 256;
        dh[idx] = hh;
        dl[idx] = __float2bfloat16(v - __bfloat162float(hh));
    }
}

// ---------------- launch -----------------------------------------------------
#define SYM(var, sym) cudaGetSymbolAddress((void**)&var, sym)

extern "C" void kernel_launch(void* const* d_in, const int* in_sizes, int n_in,
                              void* d_out, int out_size)
{
    const float* img  = (const float*)d_in[0];
    const float* txt  = (const float*)d_in[1];
    const float* tgt  = (const float*)d_in[2];
    const float* Wt   = (const float*)d_in[3];
    const float* bt   = (const float*)d_in[4];
    const float* Wi   = (const float*)d_in[5];
    const float* bi   = (const float*)d_in[6];
    const float* dsW1 = (const float*)d_in[7];
    const float* dsb1 = (const float*)d_in[8];
    const float* dsW2 = (const float*)d_in[9];
    const float* dsb2 = (const float*)d_in[10];
    const float* expW = (const float*)d_in[11];
    const float* expb = (const float*)d_in[12];
    const float* rtW1 = (const float*)d_in[13];
    const float* rtb1 = (const float*)d_in[14];
    const float* rtW2 = (const float*)d_in[15];
    const float* rtb2 = (const float*)d_in[16];
    const float* outW = (const float*)d_in[17];
    const float* outb = (const float*)d_in[18];
    const float* lsc  = (const float*)d_in[19];

    float *rth, *probs, *expert, *dsh, *ds, *res;
    SYM(rth, g_rth); SYM(probs, g_probs); SYM(expert, g_expert);
    SYM(dsh, g_dsh); SYM(ds, g_ds); SYM(res, g_res);

    bf16 *txh, *txl, *imh, *iml, *cbh, *cbl, *fuh, *ful, *prh, *prl, *tgh, *tgl;
    bf16 *wth, *wtl, *wih, *wil, *rwh, *rwl, *ewh, *ewl, *dwh, *dwl, *owh, *owl;
    SYM(txh, g_txt_h); SYM(txl, g_txt_l); SYM(imh, g_img_h); SYM(iml, g_img_l);
    SYM(cbh, g_comb_h); SYM(cbl, g_comb_l); SYM(fuh, g_fused_h); SYM(ful, g_fused_l);
    SYM(prh, g_pred_h); SYM(prl, g_pred_l); SYM(tgh, g_tgt_h); SYM(tgl, g_tgt_l);
    SYM(wth, g_Wt_h); SYM(wtl, g_Wt_l); SYM(wih, g_Wi_h); SYM(wil, g_Wi_l);
    SYM(rwh, g_rtW1_h); SYM(rwl, g_rtW1_l); SYM(ewh, g_expW_h); SYM(ewl, g_expW_l);
    SYM(dwh, g_dsW1_h); SYM(dwl, g_dsW1_l); SYM(owh, g_outW_h); SYM(owl, g_outW_l);

    float* out_logits = (float*)d_out;
    float* out_ds     = out_logits + (size_t)B_SZ * T_SZ;
    float* out_probs  = out_ds + B_SZ;

    cudaFuncSetAttribute(gemm_tc, cudaFuncAttributeMaxDynamicSharedMemorySize, SMEM_GEMM);

    // ---- split f32 inputs/weights into bf16 hi/lo ----
    split_kernel<<<(B_SZ * FD) / 256, 256>>>(txt, txh, txl);
    split_kernel<<<(B_SZ * FD) / 256, 256>>>(img, imh, iml);
    split_kernel<<<(PD * FD) / 256, 256>>>(Wt, wth, wtl);
    split_kernel<<<(PD * FD) / 256, 256>>>(Wi, wih, wil);
    split_kernel<<<(256 * CB) / 256, 256>>>(rtW1, rwh, rwl);
    split_kernel<<<(NE * HD * CB) / 256, 256>>>(expW, ewh, ewl);
    split_kernel<<<(HD * CB) / 256, 256>>>(dsW1, dwh, dwl);
    split_kernel<<<(FD * HD) / 256, 256>>>(outW, owh, owl);

    dim3 blk(256);
    // projections -> comb bf16 hi/lo (text cols 0:512, image cols 512:1024)
    gemm_tc<<<dim3(PD / 256, B_SZ / 128), blk, SMEM_GEMM>>>(
        txh, txl, wth, wtl, bt, nullptr, cbh, cbl, FD, CB, 1, nullptr);
    gemm_tc<<<dim3(PD / 256, B_SZ / 128), blk, SMEM_GEMM>>>(
        imh, iml, wih, wil, bi, nullptr, cbh + PD, cbl + PD, FD, CB, 1, nullptr);

    // router hidden [B,256] f32, then logits+softmax
    gemm_tc<<<dim3(1, B_SZ / 128), blk, SMEM_GEMM>>>(
        cbh, cbl, rwh, rwl, rtb1, rth, nullptr, nullptr, CB, 256, 1, nullptr);
    router_kernel<<<B_SZ, 128>>>(rth, rtW2, rtb2, probs, out_probs);

    // experts fused GEMM: [B, 4096] f32
    gemm_tc<<<dim3((NE * HD) / 256, B_SZ / 128), blk, SMEM_GEMM>>>(
        cbh, cbl, ewh, ewl, expb, expert, nullptr, nullptr, CB, NE * HD, 1, nullptr);

    // ds hidden [B, 1024] f32
    gemm_tc<<<dim3(HD / 256, B_SZ / 128), blk, SMEM_GEMM>>>(
        cbh, cbl, dwh, dwl, dsb1, dsh, nullptr, nullptr, CB, HD, 1, nullptr);

    // ds scalar + router-weighted expert mix -> fused bf16 hi/lo
    fuse_kernel<<<B_SZ, 256>>>(dsh, dsW2, dsb2, expert, probs, fuh, ful, ds, out_ds);

    // residual [B, 768] f32
    gemm_tc<<<dim3(FD / 256, B_SZ / 128), blk, SMEM_GEMM>>>(
        fuh, ful, owh, owl, outb, res, nullptr, nullptr, HD, FD, 0, nullptr);

    // mix + normalize -> pred/tgt bf16 hi/lo
    norm_kernel<<<B_SZ + T_SZ, 256>>>(res, txt, img, ds, tgt, prh, prl, tgh, tgl);

    // logits = exp(logit_scale) * pred @ tgt^T   [8192, 8192] f32
    gemm_tc<<<dim3(T_SZ / 256, B_SZ / 128), blk, SMEM_GEMM>>>(
        prh, prl, tgh, tgl, nullptr, out_logits, nullptr, nullptr, FD, T_SZ, 0, lsc);
}

// round 6
// speedup vs baseline: 4.1466x; 1.4048x over previous
#include <cuda_runtime.h>
#include <cuda_bf16.h>
#include <math.h>
#include <stdint.h>

#define B_SZ 8192
#define T_SZ 8192
#define FD 768
#define PD 512
#define HD 1024
#define NE 4
#define CB 1024  // 2*P

typedef __nv_bfloat16 bf16;

// ---------------- scratch (device globals; no allocation allowed) ----------
__device__ float g_rth[(size_t)B_SZ * 256];
__device__ float g_probs[(size_t)B_SZ * NE];
__device__ float g_expert[(size_t)B_SZ * NE * HD];
__device__ float g_dsh[(size_t)B_SZ * HD];
__device__ float g_ds[B_SZ];
__device__ float g_res[(size_t)B_SZ * FD];

// bf16 operand buffers; only pred/tgt need hi+lo (3-term logits GEMM)
__device__ __align__(256) bf16 g_txt_h[(size_t)B_SZ * FD];
__device__ __align__(256) bf16 g_img_h[(size_t)B_SZ * FD];
__device__ __align__(256) bf16 g_comb_h[(size_t)B_SZ * CB];
__device__ __align__(256) bf16 g_fused_h[(size_t)B_SZ * HD];
__device__ __align__(256) bf16 g_pred_h[(size_t)B_SZ * FD];
__device__ __align__(256) bf16 g_pred_l[(size_t)B_SZ * FD];
__device__ __align__(256) bf16 g_tgt_h[(size_t)T_SZ * FD];
__device__ __align__(256) bf16 g_tgt_l[(size_t)T_SZ * FD];
__device__ __align__(256) bf16 g_Wt_h[(size_t)PD * FD];
__device__ __align__(256) bf16 g_Wi_h[(size_t)PD * FD];
__device__ __align__(256) bf16 g_rtW1_h[(size_t)256 * CB];
__device__ __align__(256) bf16 g_expW_h[(size_t)NE * HD * CB];
__device__ __align__(256) bf16 g_dsW1_h[(size_t)HD * CB];
__device__ __align__(256) bf16 g_outW_h[(size_t)FD * HD];

// ---------------- helpers ---------------------------------------------------
__device__ __forceinline__ float gelu_f(float x) {
    return 0.5f * x * (1.0f + erff(x * 0.70710678118654752440f));
}

__device__ __forceinline__ uint32_t smem_u32(const void* p) {
    uint32_t a;
    asm("{ .reg .u64 t; cvta.to.shared.u64 t, %1; cvt.u32.u64 %0, t; }" : "=r"(a) : "l"(p));
    return a;
}

__device__ __forceinline__ void cpasync16(uint32_t dst, const void* src) {
    asm volatile("cp.async.cg.shared.global [%0], [%1], 16;" :: "r"(dst), "l"(src));
}
__device__ __forceinline__ void cp_commit() {
    asm volatile("cp.async.commit_group;" ::: "memory");
}
__device__ __forceinline__ void cp_wait1() {
    asm volatile("cp.async.wait_group 1;" ::: "memory");
}
__device__ __forceinline__ void cp_wait0() {
    asm volatile("cp.async.wait_group 0;" ::: "memory");
}

__device__ __forceinline__ void ldsm4(uint32_t& r0, uint32_t& r1, uint32_t& r2, uint32_t& r3,
                                      uint32_t a) {
    asm volatile("ldmatrix.sync.aligned.m8n8.x4.shared.b16 {%0,%1,%2,%3}, [%4];"
                 : "=r"(r0), "=r"(r1), "=r"(r2), "=r"(r3) : "r"(a));
}

__device__ __forceinline__ void mma16816(float* c, const uint32_t* a, uint32_t b0, uint32_t b1) {
    asm volatile(
        "mma.sync.aligned.m16n8k16.row.col.f32.bf16.bf16.f32 "
        "{%0,%1,%2,%3}, {%4,%5,%6,%7}, {%8,%9}, {%0,%1,%2,%3};"
        : "+f"(c[0]), "+f"(c[1]), "+f"(c[2]), "+f"(c[3])
        : "r"(a[0]), "r"(a[1]), "r"(a[2]), "r"(a[3]), "r"(b0), "r"(b1));
}

// ---------------- elementwise converts ---------------------------------------
__global__ void cast_kernel(const float* __restrict__ x, bf16* __restrict__ h)
{
    size_t i = (size_t)blockIdx.x * 256 + threadIdx.x;
    h[i] = __float2bfloat16(x[i]);
}

// ---------------- HMMA GEMM (templated: SPLIT=3-term hi/lo, else plain bf16) -
// C[M,N] = act( A[M,K] @ B[N,K]^T + bias ) * scale
// CTA tile 128x256, K-step 64, 8 warps (64x64 warp tiles), 2-stage cp.async.
// Stage layout: Ah @0 (16K), [Al @16K], Bh @ABOFF (32K), [Bl @+32K]
template <bool SPLIT>
__device__ __forceinline__ void load_stage(
    uint32_t sb,
    const bf16* __restrict__ Ah, const bf16* __restrict__ Al,
    const bf16* __restrict__ Bh, const bf16* __restrict__ Bl,
    int m0, int n0, int k0, int K, int t)
{
    const uint32_t BOFF = SPLIT ? 32768u : 16384u;
#pragma unroll
    for (int i = 0; i < 4; i++) {          // A: 128 rows x 8 chunks = 1024
        int id = t + (i << 8);
        int row = id >> 3, ch = id & 7;
        uint32_t off = (uint32_t)(row << 7) + (uint32_t)((ch ^ (row & 7)) << 4);
        size_t g = (size_t)(m0 + row) * K + k0 + (ch << 3);
        cpasync16(sb + off, Ah + g);
        if (SPLIT) cpasync16(sb + 16384 + off, Al + g);
    }
#pragma unroll
    for (int i = 0; i < 8; i++) {          // B: 256 rows x 8 chunks = 2048
        int id = t + (i << 8);
        int row = id >> 3, ch = id & 7;
        uint32_t off = (uint32_t)(row << 7) + (uint32_t)((ch ^ (row & 7)) << 4);
        size_t g = (size_t)(n0 + row) * K + k0 + (ch << 3);
        cpasync16(sb + BOFF + off, Bh + g);
        if (SPLIT) cpasync16(sb + BOFF + 32768 + off, Bl + g);
    }
}

#define MMA_ALL(Aset, Bset)                                            \
    do {                                                               \
        _Pragma("unroll")                                              \
        for (int mi = 0; mi < 4; mi++) {                               \
            _Pragma("unroll")                                          \
            for (int nj = 0; nj < 4; nj++) {                           \
                mma16816(acc[mi][nj * 2],     Aset[mi], Bset[nj][0], Bset[nj][1]); \
                mma16816(acc[mi][nj * 2 + 1], Aset[mi], Bset[nj][2], Bset[nj][3]); \
            }                                                          \
        }                                                              \
    } while (0)

template <bool SPLIT>
__global__ void __launch_bounds__(256, 1)
gemm_tc(const bf16* __restrict__ Ah, const bf16* __restrict__ Al,
        const bf16* __restrict__ Bh, const bf16* __restrict__ Bl,
        const float* __restrict__ bias,
        float* __restrict__ Cf, bf16* __restrict__ Chi, bf16* __restrict__ Clo,
        int K, int ldc, int act, const float* __restrict__ scale_ptr)
{
    constexpr uint32_t STAGE = SPLIT ? 98304u : 49152u;
    constexpr uint32_t BOFF  = SPLIT ? 32768u : 16384u;

    extern __shared__ __align__(128) char smem[];
    const uint32_t sb = smem_u32(smem);
    const int t = threadIdx.x;
    const int lane = t & 31, wid = t >> 5;
    const int wm = wid >> 2, wn = wid & 3;       // 2 x 4 warp grid
    const int m0 = blockIdx.y * 128;
    const int n0 = blockIdx.x * 256;

    float acc[4][8][4];
#pragma unroll
    for (int i = 0; i < 4; i++)
#pragma unroll
        for (int j = 0; j < 8; j++)
#pragma unroll
            for (int q = 0; q < 4; q++) acc[i][j][q] = 0.f;

    const int lm = lane >> 3, lr8 = lane & 7;
    const int a_rowoff = ((lm & 1) << 3) + lr8;
    const int a_choff  = (lm >> 1);
    const int b_rowoff = ((lm >> 1) << 3) + lr8;
    const int b_choff  = (lm & 1);

    const int iters = K >> 6;
    load_stage<SPLIT>(sb, Ah, Al, Bh, Bl, m0, n0, 0, K, t);
    cp_commit();

    for (int kt = 0; kt < iters; kt++) {
        const int s = kt & 1;
        if (kt + 1 < iters) {
            load_stage<SPLIT>(sb + (s ^ 1) * STAGE, Ah, Al, Bh, Bl, m0, n0, (kt + 1) << 6, K, t);
            cp_commit();
            cp_wait1();
        } else {
            cp_wait0();
        }
        __syncthreads();

        const uint32_t ss = sb + s * STAGE;
#pragma unroll 1
        for (int kk = 0; kk < 4; kk++) {
            uint32_t Ahf[4][4], Bhf[4][4], Alf[4][4], Blf[4][4];
            const int chA = 2 * kk + a_choff;
            const int chB = 2 * kk + b_choff;
            // front-load all ldmatrix so HMMA overlaps in-flight LDSM
#pragma unroll
            for (int mi = 0; mi < 4; mi++) {
                int row = wm * 64 + mi * 16 + a_rowoff;
                uint32_t ad = ss + (row << 7) + (((chA ^ (row & 7))) << 4);
                ldsm4(Ahf[mi][0], Ahf[mi][1], Ahf[mi][2], Ahf[mi][3], ad);
            }
#pragma unroll
            for (int nj = 0; nj < 4; nj++) {
                int row = wn * 64 + nj * 16 + b_rowoff;
                uint32_t ad = ss + BOFF + (row << 7) + (((chB ^ (row & 7))) << 4);
                ldsm4(Bhf[nj][0], Bhf[nj][1], Bhf[nj][2], Bhf[nj][3], ad);
            }
            if (SPLIT) {
#pragma unroll
                for (int nj = 0; nj < 4; nj++) {
                    int row = wn * 64 + nj * 16 + b_rowoff;
                    uint32_t ad = ss + BOFF + 32768 + (row << 7) + (((chB ^ (row & 7))) << 4);
                    ldsm4(Blf[nj][0], Blf[nj][1], Blf[nj][2], Blf[nj][3], ad);
                }
#pragma unroll
                for (int mi = 0; mi < 4; mi++) {
                    int row = wm * 64 + mi * 16 + a_rowoff;
                    uint32_t ad = ss + 16384 + (row << 7) + (((chA ^ (row & 7))) << 4);
                    ldsm4(Alf[mi][0], Alf[mi][1], Alf[mi][2], Alf[mi][3], ad);
                }
            }
            MMA_ALL(Ahf, Bhf);
            if (SPLIT) {
                MMA_ALL(Ahf, Blf);
                MMA_ALL(Alf, Bhf);
            }
        }
        __syncthreads();
    }

    // epilogue: direct stores from accumulators
    const float scale = scale_ptr ? expf(scale_ptr[0]) : 1.0f;
    const int lr = lane >> 2, lc = (lane & 3) * 2;
#pragma unroll
    for (int mi = 0; mi < 4; mi++) {
#pragma unroll
        for (int nj = 0; nj < 4; nj++) {
#pragma unroll
            for (int h = 0; h < 2; h++) {
                int col = n0 + wn * 64 + nj * 16 + h * 8 + lc;
                float bx = 0.f, by = 0.f;
                if (bias) { float2 bb = *(const float2*)(bias + col); bx = bb.x; by = bb.y; }
#pragma unroll
                for (int rh = 0; rh < 2; rh++) {
                    int row = m0 + wm * 64 + mi * 16 + rh * 8 + lr;
                    float v0 = acc[mi][nj * 2 + h][rh * 2 + 0] + bx;
                    float v1 = acc[mi][nj * 2 + h][rh * 2 + 1] + by;
                    if (act) { v0 = gelu_f(v0); v1 = gelu_f(v1); }
                    v0 *= scale; v1 *= scale;
                    size_t idx = (size_t)row * ldc + col;
                    if (Cf) *(float2*)(Cf + idx) = make_float2(v0, v1);
                    if (Chi) {
                        bf16 h0 = __float2bfloat16(v0);
                        bf16 h1 = __float2bfloat16(v1);
                        *(__nv_bfloat162*)(Chi + idx) = __nv_bfloat162(h0, h1);
                        if (Clo) {
                            *(__nv_bfloat162*)(Clo + idx) = __nv_bfloat162(
                                __float2bfloat16(v0 - __bfloat162float(h0)),
                                __float2bfloat16(v1 - __bfloat162float(h1)));
                        }
                    }
                }
            }
        }
    }
}

// ---------------- router: logits (4 x 256-dot) + softmax --------------------
__global__ void router_kernel(const float* __restrict__ rth,
                              const float* __restrict__ W2,
                              const float* __restrict__ b2,
                              float* __restrict__ probs_buf,
                              float* __restrict__ out_probs)
{
    int b = blockIdx.x;
    int lane = threadIdx.x & 31;
    int w = threadIdx.x >> 5;
    const float* x = rth + (size_t)b * 256;
    const float* wr = W2 + (size_t)w * 256;
    float s = 0.f;
    for (int i = lane; i < 256; i += 32) s += x[i] * wr[i];
#pragma unroll
    for (int o = 16; o; o >>= 1) s += __shfl_xor_sync(0xffffffffu, s, o);
    __shared__ float sl[4];
    if (lane == 0) sl[w] = s + b2[w];
    __syncthreads();
    if (threadIdx.x == 0) {
        float m = fmaxf(fmaxf(sl[0], sl[1]), fmaxf(sl[2], sl[3]));
        float e[4]; float sum = 0.f;
#pragma unroll
        for (int i = 0; i < 4; i++) { e[i] = expf(sl[i] - m); sum += e[i]; }
        float inv = 1.f / sum;
#pragma unroll
        for (int i = 0; i < 4; i++) {
            float p = e[i] * inv;
            probs_buf[(size_t)b * 4 + i] = p;
            out_probs[(size_t)b * 4 + i] = p;
        }
    }
}

// ---------------- ds scalar + MoE mix (emits fused as bf16 hi) ---------------
__global__ void fuse_kernel(const float* __restrict__ dsh,
                            const float* __restrict__ dsW2,
                            const float* __restrict__ dsb2,
                            const float* __restrict__ expert,
                            const float* __restrict__ probs,
                            bf16* __restrict__ fusedh,
                            float* __restrict__ ds_buf,
                            float* __restrict__ out_ds)
{
    int b = blockIdx.x;
    int t = threadIdx.x;  // 256
    const float* xr = dsh + (size_t)b * HD;
    float s = 0.f;
    for (int k = t; k < HD; k += 256) s += xr[k] * dsW2[k];
    __shared__ float red[256];
    red[t] = s;
    __syncthreads();
    for (int off = 128; off; off >>= 1) {
        if (t < off) red[t] += red[t + off];
        __syncthreads();
    }
    if (t == 0) {
        float d = 1.f / (1.f + expf(-(red[0] + dsb2[0])));
        ds_buf[b] = d;
        out_ds[b] = d;
    }
    float p0 = probs[(size_t)b * 4 + 0], p1 = probs[(size_t)b * 4 + 1];
    float p2 = probs[(size_t)b * 4 + 2], p3 = probs[(size_t)b * 4 + 3];
    const float* eb = expert + (size_t)b * (NE * HD);
    for (int h = t; h < HD; h += 256) {
        float v = p0 * eb[h] + p1 * eb[HD + h] + p2 * eb[2 * HD + h] + p3 * eb[3 * HD + h];
        fusedh[(size_t)b * HD + h] = __float2bfloat16(v);
    }
}

// ---------------- mix + L2 normalize, emit bf16 hi/lo ------------------------
__global__ void norm_kernel(const float* __restrict__ res,
                            const float* __restrict__ text,
                            const float* __restrict__ img,
                            const float* __restrict__ ds_buf,
                            const float* __restrict__ target,
                            bf16* __restrict__ predh, bf16* __restrict__ predl,
                            bf16* __restrict__ tgth,  bf16* __restrict__ tgtl)
{
    int r = blockIdx.x;
    int t = threadIdx.x;  // 256, row length 768 = 3*256
    float o[3];
    bf16 *dh, *dl;
    size_t base;
    if (r < B_SZ) {
        float d = ds_buf[r];
        base = (size_t)r * FD;
#pragma unroll
        for (int i = 0; i < 3; i++) {
            int j = t + i * 256;
            o[i] = d * text[base + j] + (1.0f - d) * img[base + j] + res[base + j];
        }
        dh = predh; dl = predl;
    } else {
        base = (size_t)(r - B_SZ) * FD;
#pragma unroll
        for (int i = 0; i < 3; i++) o[i] = target[base + t + i * 256];
        dh = tgth; dl = tgtl;
    }
    float s = o[0] * o[0] + o[1] * o[1] + o[2] * o[2];
    __shared__ float red[256];
    red[t] = s;
    __syncthreads();
    for (int off = 128; off; off >>= 1) {
        if (t < off) red[t] += red[t + off];
        __syncthreads();
    }
    __shared__ float inv_s;
    if (t == 0) inv_s = 1.0f / fmaxf(sqrtf(red[0]), 1e-12f);
    __syncthreads();
    float inv = inv_s;
#pragma unroll
    for (int i = 0; i < 3; i++) {
        float v = o[i] * inv;
        bf16 hh = __float2bfloat16(v);
        size_t idx = base + t + i * 256;
        dh[idx] = hh;
        dl[idx] = __float2bfloat16(v - __bfloat162float(hh));
    }
}

// ---------------- launch -----------------------------------------------------
#define SYM(var, sym) cudaGetSymbolAddress((void**)&var, sym)

extern "C" void kernel_launch(void* const* d_in, const int* in_sizes, int n_in,
                              void* d_out, int out_size)
{
    const float* img  = (const float*)d_in[0];
    const float* txt  = (const float*)d_in[1];
    const float* tgt  = (const float*)d_in[2];
    const float* Wt   = (const float*)d_in[3];
    const float* bt   = (const float*)d_in[4];
    const float* Wi   = (const float*)d_in[5];
    const float* bi   = (const float*)d_in[6];
    const float* dsW1 = (const float*)d_in[7];
    const float* dsb1 = (const float*)d_in[8];
    const float* dsW2 = (const float*)d_in[9];
    const float* dsb2 = (const float*)d_in[10];
    const float* expW = (const float*)d_in[11];
    const float* expb = (const float*)d_in[12];
    const float* rtW1 = (const float*)d_in[13];
    const float* rtb1 = (const float*)d_in[14];
    const float* rtW2 = (const float*)d_in[15];
    const float* rtb2 = (const float*)d_in[16];
    const float* outW = (const float*)d_in[17];
    const float* outb = (const float*)d_in[18];
    const float* lsc  = (const float*)d_in[19];

    float *rth, *probs, *expert, *dsh, *ds, *res;
    SYM(rth, g_rth); SYM(probs, g_probs); SYM(expert, g_expert);
    SYM(dsh, g_dsh); SYM(ds, g_ds); SYM(res, g_res);

    bf16 *txh, *imh, *cbh, *fuh, *prh, *prl, *tgh, *tgl;
    bf16 *wth, *wih, *rwh, *ewh, *dwh, *owh;
    SYM(txh, g_txt_h); SYM(imh, g_img_h);
    SYM(cbh, g_comb_h); SYM(fuh, g_fused_h);
    SYM(prh, g_pred_h); SYM(prl, g_pred_l); SYM(tgh, g_tgt_h); SYM(tgl, g_tgt_l);
    SYM(wth, g_Wt_h); SYM(wih, g_Wi_h); SYM(rwh, g_rtW1_h);
    SYM(ewh, g_expW_h); SYM(dwh, g_dsW1_h); SYM(owh, g_outW_h);

    float* out_logits = (float*)d_out;
    float* out_ds     = out_logits + (size_t)B_SZ * T_SZ;
    float* out_probs  = out_ds + B_SZ;

    cudaFuncSetAttribute(gemm_tc<false>, cudaFuncAttributeMaxDynamicSharedMemorySize, 2 * 49152);
    cudaFuncSetAttribute(gemm_tc<true>,  cudaFuncAttributeMaxDynamicSharedMemorySize, 2 * 98304);

    // ---- cast f32 -> bf16 (hi only; inputs + all weights) ----
    cast_kernel<<<(B_SZ * FD) / 256, 256>>>(txt, txh);
    cast_kernel<<<(B_SZ * FD) / 256, 256>>>(img, imh);
    cast_kernel<<<(PD * FD) / 256, 256>>>(Wt, wth);
    cast_kernel<<<(PD * FD) / 256, 256>>>(Wi, wih);
    cast_kernel<<<(256 * CB) / 256, 256>>>(rtW1, rwh);
    cast_kernel<<<(NE * HD * CB) / 256, 256>>>(expW, ewh);
    cast_kernel<<<(HD * CB) / 256, 256>>>(dsW1, dwh);
    cast_kernel<<<(FD * HD) / 256, 256>>>(outW, owh);

    dim3 blk(256);
    // projections -> comb bf16 (text cols 0:512, image cols 512:1024)
    gemm_tc<false><<<dim3(PD / 256, B_SZ / 128), blk, 2 * 49152>>>(
        txh, nullptr, wth, nullptr, bt, nullptr, cbh, nullptr, FD, CB, 1, nullptr);
    gemm_tc<false><<<dim3(PD / 256, B_SZ / 128), blk, 2 * 49152>>>(
        imh, nullptr, wih, nullptr, bi, nullptr, cbh + PD, nullptr, FD, CB, 1, nullptr);

    // router hidden [B,256] f32, then logits+softmax
    gemm_tc<false><<<dim3(1, B_SZ / 128), blk, 2 * 49152>>>(
        cbh, nullptr, rwh, nullptr, rtb1, rth, nullptr, nullptr, CB, 256, 1, nullptr);
    router_kernel<<<B_SZ, 128>>>(rth, rtW2, rtb2, probs, out_probs);

    // experts fused GEMM: [B, 4096] f32
    gemm_tc<false><<<dim3((NE * HD) / 256, B_SZ / 128), blk, 2 * 49152>>>(
        cbh, nullptr, ewh, nullptr, expb, expert, nullptr, nullptr, CB, NE * HD, 1, nullptr);

    // ds hidden [B, 1024] f32
    gemm_tc<false><<<dim3(HD / 256, B_SZ / 128), blk, 2 * 49152>>>(
        cbh, nullptr, dwh, nullptr, dsb1, dsh, nullptr, nullptr, CB, HD, 1, nullptr);

    // ds scalar + router-weighted expert mix -> fused bf16
    fuse_kernel<<<B_SZ, 256>>>(dsh, dsW2, dsb2, expert, probs, fuh, ds, out_ds);

    // residual [B, 768] f32
    gemm_tc<false><<<dim3(FD / 256, B_SZ / 128), blk, 2 * 49152>>>(
        fuh, nullptr, owh, nullptr, outb, res, nullptr, nullptr, HD, FD, 0, nullptr);

    // mix + normalize -> pred/tgt bf16 hi/lo
    norm_kernel<<<B_SZ + T_SZ, 256>>>(res, txt, img, ds, tgt, prh, prl, tgh, tgl);

    // logits = exp(logit_scale) * pred @ tgt^T   [8192, 8192] f32 (3-term split)
    gemm_tc<true><<<dim3(T_SZ / 256, B_SZ / 128), blk, 2 * 98304>>>(
        prh, prl, tgh, tgl, nullptr, out_logits, nullptr, nullptr, FD, T_SZ, 0, lsc);
}

// round 7
// speedup vs baseline: 6.1585x; 1.4852x over previous
#include <cuda_runtime.h>
#include <cuda_fp16.h>
#include <math.h>
#include <stdint.h>

#define B_SZ 8192
#define T_SZ 8192
#define FD 768
#define PD 512
#define HD 1024
#define NE 4
#define CB 1024  // 2*P

typedef __half fp16;

// ---------------- scratch (device globals; no allocation allowed) ----------
__device__ float g_rth[(size_t)B_SZ * 256];
__device__ float g_probs[(size_t)B_SZ * NE];
__device__ fp16  g_expert[(size_t)B_SZ * NE * HD];
__device__ float g_dsh[(size_t)B_SZ * HD];
__device__ float g_ds[B_SZ];
__device__ float g_res[(size_t)B_SZ * FD];

__device__ __align__(256) fp16 g_txt_h[(size_t)B_SZ * FD];
__device__ __align__(256) fp16 g_img_h[(size_t)B_SZ * FD];
__device__ __align__(256) fp16 g_comb_h[(size_t)B_SZ * CB];
__device__ __align__(256) fp16 g_fused_h[(size_t)B_SZ * HD];
__device__ __align__(256) fp16 g_pred_h[(size_t)B_SZ * FD];
__device__ __align__(256) fp16 g_tgt_h[(size_t)T_SZ * FD];
__device__ __align__(256) fp16 g_Wt_h[(size_t)PD * FD];
__device__ __align__(256) fp16 g_Wi_h[(size_t)PD * FD];
__device__ __align__(256) fp16 g_rtW1_h[(size_t)256 * CB];
__device__ __align__(256) fp16 g_expW_h[(size_t)NE * HD * CB];
__device__ __align__(256) fp16 g_dsW1_h[(size_t)HD * CB];
__device__ __align__(256) fp16 g_outW_h[(size_t)FD * HD];

// ---------------- helpers ---------------------------------------------------
__device__ __forceinline__ float gelu_f(float x) {
    return 0.5f * x * (1.0f + erff(x * 0.70710678118654752440f));
}

__device__ __forceinline__ uint32_t smem_u32(const void* p) {
    uint32_t a;
    asm("{ .reg .u64 t; cvta.to.shared.u64 t, %1; cvt.u32.u64 %0, t; }" : "=r"(a) : "l"(p));
    return a;
}

__device__ __forceinline__ void cpasync16(uint32_t dst, const void* src) {
    asm volatile("cp.async.cg.shared.global [%0], [%1], 16;" :: "r"(dst), "l"(src));
}
__device__ __forceinline__ void cp_commit() {
    asm volatile("cp.async.commit_group;" ::: "memory");
}
__device__ __forceinline__ void cp_wait2() {
    asm volatile("cp.async.wait_group 2;" ::: "memory");
}
__device__ __forceinline__ void cp_wait1() {
    asm volatile("cp.async.wait_group 1;" ::: "memory");
}
__device__ __forceinline__ void cp_wait0() {
    asm volatile("cp.async.wait_group 0;" ::: "memory");
}

__device__ __forceinline__ void ldsm4(uint32_t& r0, uint32_t& r1, uint32_t& r2, uint32_t& r3,
                                      uint32_t a) {
    asm volatile("ldmatrix.sync.aligned.m8n8.x4.shared.b16 {%0,%1,%2,%3}, [%4];"
                 : "=r"(r0), "=r"(r1), "=r"(r2), "=r"(r3) : "r"(a));
}

__device__ __forceinline__ void mma16816(float* c, const uint32_t* a, uint32_t b0, uint32_t b1) {
    asm volatile(
        "mma.sync.aligned.m16n8k16.row.col.f32.f16.f16.f32 "
        "{%0,%1,%2,%3}, {%4,%5,%6,%7}, {%8,%9}, {%0,%1,%2,%3};"
        : "+f"(c[0]), "+f"(c[1]), "+f"(c[2]), "+f"(c[3])
        : "r"(a[0]), "r"(a[1]), "r"(a[2]), "r"(a[3]), "r"(b0), "r"(b1));
}

// ---------------- elementwise convert ----------------------------------------
__global__ void cast_kernel(const float* __restrict__ x, fp16* __restrict__ h)
{
    size_t i = ((size_t)blockIdx.x * 256 + threadIdx.x) * 4;
    float4 v = *(const float4*)(x + i);
    __half2 a = __floats2half2_rn(v.x, v.y);
    __half2 b = __floats2half2_rn(v.z, v.w);
    *(__half2*)(h + i)     = a;
    *(__half2*)(h + i + 2) = b;
}

// ---------------- fp16 HMMA GEMM ---------------------------------------------
// C[M,N] = act( A[M,K] @ B[N,K]^T + bias ) * scale
// CTA tile 128x256, K-step 64, 8 warps (64x64 warp tiles), 3-stage cp.async.
// Stage layout: A @0 (16K), B @16384 (32K). STAGE = 48K, 3 stages = 144K smem.
#define STAGE 49152u
#define SMEM_GEMM (3 * STAGE)

__device__ __forceinline__ void load_stage(
    uint32_t sb,
    const fp16* __restrict__ A, const fp16* __restrict__ B,
    int m0, int n0, int k0, int K, int t)
{
#pragma unroll
    for (int i = 0; i < 4; i++) {          // A: 128 rows x 8 chunks = 1024
        int id = t + (i << 8);
        int row = id >> 3, ch = id & 7;
        uint32_t off = (uint32_t)(row << 7) + (uint32_t)((ch ^ (row & 7)) << 4);
        cpasync16(sb + off, A + (size_t)(m0 + row) * K + k0 + (ch << 3));
    }
#pragma unroll
    for (int i = 0; i < 8; i++) {          // B: 256 rows x 8 chunks = 2048
        int id = t + (i << 8);
        int row = id >> 3, ch = id & 7;
        uint32_t off = (uint32_t)(row << 7) + (uint32_t)((ch ^ (row & 7)) << 4);
        cpasync16(sb + 16384 + off, B + (size_t)(n0 + row) * K + k0 + (ch << 3));
    }
}

__global__ void __launch_bounds__(256, 1)
gemm_tc(const fp16* __restrict__ A, const fp16* __restrict__ B,
        const float* __restrict__ bias,
        float* __restrict__ Cf, fp16* __restrict__ Ch,
        int K, int ldc, int act, const float* __restrict__ scale_ptr)
{
    extern __shared__ __align__(128) char smem[];
    const uint32_t sb = smem_u32(smem);
    const int t = threadIdx.x;
    const int lane = t & 31, wid = t >> 5;
    const int wm = wid >> 2, wn = wid & 3;       // 2 x 4 warp grid
    const int m0 = blockIdx.y * 128;
    const int n0 = blockIdx.x * 256;

    float acc[4][8][4];
#pragma unroll
    for (int i = 0; i < 4; i++)
#pragma unroll
        for (int j = 0; j < 8; j++)
#pragma unroll
            for (int q = 0; q < 4; q++) acc[i][j][q] = 0.f;

    const int lm = lane >> 3, lr8 = lane & 7;
    const int a_rowoff = ((lm & 1) << 3) + lr8;
    const int a_choff  = (lm >> 1);
    const int b_rowoff = ((lm >> 1) << 3) + lr8;
    const int b_choff  = (lm & 1);

    const int iters = K >> 6;

    // prologue: fill up to 2 stages
    load_stage(sb, A, B, m0, n0, 0, K, t);
    cp_commit();
    if (iters > 1) {
        load_stage(sb + STAGE, A, B, m0, n0, 64, K, t);
        cp_commit();
    }

    for (int kt = 0; kt < iters; kt++) {
        if (kt + 2 < iters) {
            load_stage(sb + (uint32_t)((kt + 2) % 3) * STAGE, A, B, m0, n0, (kt + 2) << 6, K, t);
            cp_commit();
        }
        // wait for stage kt (groups committed after it: up to 2)
        int after = (iters - 1 < kt + 2 ? iters - 1 : kt + 2) - kt;
        if (after >= 2) cp_wait2();
        else if (after == 1) cp_wait1();
        else cp_wait0();
        __syncthreads();

        const uint32_t ss = sb + (uint32_t)(kt % 3) * STAGE;
#pragma unroll 1
        for (int kk = 0; kk < 4; kk++) {
            uint32_t Af[4][4], Bf[4][4];
            const int chA = 2 * kk + a_choff;
            const int chB = 2 * kk + b_choff;
#pragma unroll
            for (int mi = 0; mi < 4; mi++) {
                int row = wm * 64 + mi * 16 + a_rowoff;
                uint32_t ad = ss + (row << 7) + (((chA ^ (row & 7))) << 4);
                ldsm4(Af[mi][0], Af[mi][1], Af[mi][2], Af[mi][3], ad);
            }
#pragma unroll
            for (int nj = 0; nj < 4; nj++) {
                int row = wn * 64 + nj * 16 + b_rowoff;
                uint32_t ad = ss + 16384 + (row << 7) + (((chB ^ (row & 7))) << 4);
                ldsm4(Bf[nj][0], Bf[nj][1], Bf[nj][2], Bf[nj][3], ad);
            }
#pragma unroll
            for (int mi = 0; mi < 4; mi++) {
#pragma unroll
                for (int nj = 0; nj < 4; nj++) {
                    mma16816(acc[mi][nj * 2],     Af[mi], Bf[nj][0], Bf[nj][1]);
                    mma16816(acc[mi][nj * 2 + 1], Af[mi], Bf[nj][2], Bf[nj][3]);
                }
            }
        }
        __syncthreads();
    }

    // epilogue: direct stores from accumulators
    const float scale = scale_ptr ? expf(scale_ptr[0]) : 1.0f;
    const int lr = lane >> 2, lc = (lane & 3) * 2;
#pragma unroll
    for (int mi = 0; mi < 4; mi++) {
#pragma unroll
        for (int nj = 0; nj < 4; nj++) {
#pragma unroll
            for (int h = 0; h < 2; h++) {
                int col = n0 + wn * 64 + nj * 16 + h * 8 + lc;
                float bx = 0.f, by = 0.f;
                if (bias) { float2 bb = *(const float2*)(bias + col); bx = bb.x; by = bb.y; }
#pragma unroll
                for (int rh = 0; rh < 2; rh++) {
                    int row = m0 + wm * 64 + mi * 16 + rh * 8 + lr;
                    float v0 = acc[mi][nj * 2 + h][rh * 2 + 0] + bx;
                    float v1 = acc[mi][nj * 2 + h][rh * 2 + 1] + by;
                    if (act) { v0 = gelu_f(v0); v1 = gelu_f(v1); }
                    v0 *= scale; v1 *= scale;
                    size_t idx = (size_t)row * ldc + col;
                    if (Cf) *(float2*)(Cf + idx) = make_float2(v0, v1);
                    if (Ch) *(__half2*)(Ch + idx) = __floats2half2_rn(v0, v1);
                }
            }
        }
    }
}

// ---------------- router: logits (4 x 256-dot) + softmax --------------------
__global__ void router_kernel(const float* __restrict__ rth,
                              const float* __restrict__ W2,
                              const float* __restrict__ b2,
                              float* __restrict__ probs_buf,
                              float* __restrict__ out_probs)
{
    int b = blockIdx.x;
    int lane = threadIdx.x & 31;
    int w = threadIdx.x >> 5;
    const float* x = rth + (size_t)b * 256;
    const float* wr = W2 + (size_t)w * 256;
    float s = 0.f;
    for (int i = lane; i < 256; i += 32) s += x[i] * wr[i];
#pragma unroll
    for (int o = 16; o; o >>= 1) s += __shfl_xor_sync(0xffffffffu, s, o);
    __shared__ float sl[4];
    if (lane == 0) sl[w] = s + b2[w];
    __syncthreads();
    if (threadIdx.x == 0) {
        float m = fmaxf(fmaxf(sl[0], sl[1]), fmaxf(sl[2], sl[3]));
        float e[4]; float sum = 0.f;
#pragma unroll
        for (int i = 0; i < 4; i++) { e[i] = expf(sl[i] - m); sum += e[i]; }
        float inv = 1.f / sum;
#pragma unroll
        for (int i = 0; i < 4; i++) {
            float p = e[i] * inv;
            probs_buf[(size_t)b * 4 + i] = p;
            out_probs[(size_t)b * 4 + i] = p;
        }
    }
}

// ---------------- ds scalar + MoE mix (expert is fp16; emits fused fp16) -----
__global__ void fuse_kernel(const float* __restrict__ dsh,
                            const float* __restrict__ dsW2,
                            const float* __restrict__ dsb2,
                            const fp16* __restrict__ expert,
                            const float* __restrict__ probs,
                            fp16* __restrict__ fusedh,
                            float* __restrict__ ds_buf,
                            float* __restrict__ out_ds)
{
    int b = blockIdx.x;
    int t = threadIdx.x;  // 256
    const float* xr = dsh + (size_t)b * HD;
    float s = 0.f;
    for (int k = t; k < HD; k += 256) s += xr[k] * dsW2[k];
    __shared__ float red[256];
    red[t] = s;
    __syncthreads();
    for (int off = 128; off; off >>= 1) {
        if (t < off) red[t] += red[t + off];
        __syncthreads();
    }
    if (t == 0) {
        float d = 1.f / (1.f + expf(-(red[0] + dsb2[0])));
        ds_buf[b] = d;
        out_ds[b] = d;
    }
    float p0 = probs[(size_t)b * 4 + 0], p1 = probs[(size_t)b * 4 + 1];
    float p2 = probs[(size_t)b * 4 + 2], p3 = probs[(size_t)b * 4 + 3];
    const fp16* eb = expert + (size_t)b * (NE * HD);
    for (int h = t; h < HD; h += 256) {
        float v = p0 * __half2float(eb[h])      + p1 * __half2float(eb[HD + h])
                + p2 * __half2float(eb[2 * HD + h]) + p3 * __half2float(eb[3 * HD + h]);
        fusedh[(size_t)b * HD + h] = __float2half_rn(v);
    }
}

// ---------------- mix + L2 normalize, emit fp16 -------------------------------
__global__ void norm_kernel(const float* __restrict__ res,
                            const float* __restrict__ text,
                            const float* __restrict__ img,
                            const float* __restrict__ ds_buf,
                            const float* __restrict__ target,
                            fp16* __restrict__ predh,
                            fp16* __restrict__ tgth)
{
    int r = blockIdx.x;
    int t = threadIdx.x;  // 256, row length 768 = 3*256
    float o[3];
    fp16* dh;
    size_t base;
    if (r < B_SZ) {
        float d = ds_buf[r];
        base = (size_t)r * FD;
#pragma unroll
        for (int i = 0; i < 3; i++) {
            int j = t + i * 256;
            o[i] = d * text[base + j] + (1.0f - d) * img[base + j] + res[base + j];
        }
        dh = predh;
    } else {
        base = (size_t)(r - B_SZ) * FD;
#pragma unroll
        for (int i = 0; i < 3; i++) o[i] = target[base + t + i * 256];
        dh = tgth;
    }
    float s = o[0] * o[0] + o[1] * o[1] + o[2] * o[2];
    __shared__ float red[256];
    red[t] = s;
    __syncthreads();
    for (int off = 128; off; off >>= 1) {
        if (t < off) red[t] += red[t + off];
        __syncthreads();
    }
    __shared__ float inv_s;
    if (t == 0) inv_s = 1.0f / fmaxf(sqrtf(red[0]), 1e-12f);
    __syncthreads();
    float inv = inv_s;
#pragma unroll
    for (int i = 0; i < 3; i++)
        dh[base + t + i * 256] = __float2half_rn(o[i] * inv);
}

// ---------------- launch -----------------------------------------------------
#define SYM(var, sym) cudaGetSymbolAddress((void**)&var, sym)

extern "C" void kernel_launch(void* const* d_in, const int* in_sizes, int n_in,
                              void* d_out, int out_size)
{
    const float* img  = (const float*)d_in[0];
    const float* txt  = (const float*)d_in[1];
    const float* tgt  = (const float*)d_in[2];
    const float* Wt   = (const float*)d_in[3];
    const float* bt   = (const float*)d_in[4];
    const float* Wi   = (const float*)d_in[5];
    const float* bi   = (const float*)d_in[6];
    const float* dsW1 = (const float*)d_in[7];
    const float* dsb1 = (const float*)d_in[8];
    const float* dsW2 = (const float*)d_in[9];
    const float* dsb2 = (const float*)d_in[10];
    const float* expW = (const float*)d_in[11];
    const float* expb = (const float*)d_in[12];
    const float* rtW1 = (const float*)d_in[13];
    const float* rtb1 = (const float*)d_in[14];
    const float* rtW2 = (const float*)d_in[15];
    const float* rtb2 = (const float*)d_in[16];
    const float* outW = (const float*)d_in[17];
    const float* outb = (const float*)d_in[18];
    const float* lsc  = (const float*)d_in[19];

    float *rth, *probs, *dsh, *ds, *res;
    fp16 *expert;
    SYM(rth, g_rth); SYM(probs, g_probs); SYM(expert, g_expert);
    SYM(dsh, g_dsh); SYM(ds, g_ds); SYM(res, g_res);

    fp16 *txh, *imh, *cbh, *fuh, *prh, *tgh;
    fp16 *wth, *wih, *rwh, *ewh, *dwh, *owh;
    SYM(txh, g_txt_h); SYM(imh, g_img_h);
    SYM(cbh, g_comb_h); SYM(fuh, g_fused_h);
    SYM(prh, g_pred_h); SYM(tgh, g_tgt_h);
    SYM(wth, g_Wt_h); SYM(wih, g_Wi_h); SYM(rwh, g_rtW1_h);
    SYM(ewh, g_expW_h); SYM(dwh, g_dsW1_h); SYM(owh, g_outW_h);

    float* out_logits = (float*)d_out;
    float* out_ds     = out_logits + (size_t)B_SZ * T_SZ;
    float* out_probs  = out_ds + B_SZ;

    cudaFuncSetAttribute(gemm_tc, cudaFuncAttributeMaxDynamicSharedMemorySize, SMEM_GEMM);

    // ---- cast f32 -> fp16 (inputs + all GEMM weights), 4 elems/thread ----
    cast_kernel<<<(B_SZ * FD) / 1024, 256>>>(txt, txh);
    cast_kernel<<<(B_SZ * FD) / 1024, 256>>>(img, imh);
    cast_kernel<<<(PD * FD) / 1024, 256>>>(Wt, wth);
    cast_kernel<<<(PD * FD) / 1024, 256>>>(Wi, wih);
    cast_kernel<<<(256 * CB) / 1024, 256>>>(rtW1, rwh);
    cast_kernel<<<(NE * HD * CB) / 1024, 256>>>(expW, ewh);
    cast_kernel<<<(HD * CB) / 1024, 256>>>(dsW1, dwh);
    cast_kernel<<<(FD * HD) / 1024, 256>>>(outW, owh);

    dim3 blk(256);
    // projections -> comb fp16 (text cols 0:512, image cols 512:1024)
    gemm_tc<<<dim3(PD / 256, B_SZ / 128), blk, SMEM_GEMM>>>(
        txh, wth, bt, nullptr, cbh, FD, CB, 1, nullptr);
    gemm_tc<<<dim3(PD / 256, B_SZ / 128), blk, SMEM_GEMM>>>(
        imh, wih, bi, nullptr, cbh + PD, FD, CB, 1, nullptr);

    // router hidden [B,256] f32, then logits+softmax
    gemm_tc<<<dim3(1, B_SZ / 128), blk, SMEM_GEMM>>>(
        cbh, rwh, rtb1, rth, nullptr, CB, 256, 1, nullptr);
    router_kernel<<<B_SZ, 128>>>(rth, rtW2, rtb2, probs, out_probs);

    // experts fused GEMM: [B, 4096] fp16
    gemm_tc<<<dim3((NE * HD) / 256, B_SZ / 128), blk, SMEM_GEMM>>>(
        cbh, ewh, expb, nullptr, expert, CB, NE * HD, 1, nullptr);

    // ds hidden [B, 1024] f32
    gemm_tc<<<dim3(HD / 256, B_SZ / 128), blk, SMEM_GEMM>>>(
        cbh, dwh, dsb1, dsh, nullptr, CB, HD, 1, nullptr);

    // ds scalar + router-weighted expert mix -> fused fp16
    fuse_kernel<<<B_SZ, 256>>>(dsh, dsW2, dsb2, expert, probs, fuh, ds, out_ds);

    // residual [B, 768] f32
    gemm_tc<<<dim3(FD / 256, B_SZ / 128), blk, SMEM_GEMM>>>(
        fuh, owh, outb, res, nullptr, HD, FD, 0, nullptr);

    // mix + normalize -> pred/tgt fp16
    norm_kernel<<<B_SZ + T_SZ, 256>>>(res, txt, img, ds, tgt, prh, tgh);

    // logits = exp(logit_scale) * pred @ tgt^T   [8192, 8192] f32, fp16 single-pass
    gemm_tc<<<dim3(T_SZ / 256, B_SZ / 128), blk, SMEM_GEMM>>>(
        prh, tgh, nullptr, out_logits, nullptr, FD, T_SZ, 0, lsc);
}

// round 8
// speedup vs baseline: 6.9373x; 1.1265x over previous
#include <cuda_runtime.h>
#include <cuda_fp16.h>
#include <math.h>
#include <stdint.h>

#define B_SZ 8192
#define T_SZ 8192
#define FD 768
#define PD 512
#define HD 1024
#define NE 4
#define CB 1024   // 2*P
#define NH 5376   // fused hidden: 4096 expert | 1024 ds | 256 router

typedef __half fp16;

// ---------------- scratch (device globals; no allocation allowed) ----------
__device__ float g_probs[(size_t)B_SZ * NE];
__device__ float g_ds[B_SZ];
__device__ float g_res[(size_t)B_SZ * FD];
__device__ fp16  g_hid[(size_t)B_SZ * NH];           // 88 MB fused hidden

__device__ __align__(256) fp16 g_txt_h[(size_t)B_SZ * FD];
__device__ __align__(256) fp16 g_img_h[(size_t)B_SZ * FD];
__device__ __align__(256) fp16 g_comb_h[(size_t)B_SZ * CB];
__device__ __align__(256) fp16 g_fused_h[(size_t)B_SZ * HD];
__device__ __align__(256) fp16 g_pred_h[(size_t)B_SZ * FD];
__device__ __align__(256) fp16 g_tgt_h[(size_t)T_SZ * FD];
__device__ __align__(256) fp16 g_Wt_h[(size_t)PD * FD];
__device__ __align__(256) fp16 g_Wi_h[(size_t)PD * FD];
__device__ __align__(256) fp16 g_bigW[(size_t)NH * CB];   // [expW | dsW1 | rtW1]
__device__ __align__(256) float g_bigB[NH];
__device__ __align__(256) fp16 g_outW_h[(size_t)FD * HD];

// ---------------- helpers ---------------------------------------------------
__device__ __forceinline__ float gelu_f(float x) {
    return 0.5f * x * (1.0f + erff(x * 0.70710678118654752440f));
}

__device__ __forceinline__ uint32_t smem_u32(const void* p) {
    uint32_t a;
    asm("{ .reg .u64 t; cvta.to.shared.u64 t, %1; cvt.u32.u64 %0, t; }" : "=r"(a) : "l"(p));
    return a;
}

__device__ __forceinline__ void cpasync16(uint32_t dst, const void* src) {
    asm volatile("cp.async.cg.shared.global [%0], [%1], 16;" :: "r"(dst), "l"(src));
}
__device__ __forceinline__ void cp_commit() {
    asm volatile("cp.async.commit_group;" ::: "memory");
}
__device__ __forceinline__ void cp_wait2() {
    asm volatile("cp.async.wait_group 2;" ::: "memory");
}
__device__ __forceinline__ void cp_wait1() {
    asm volatile("cp.async.wait_group 1;" ::: "memory");
}
__device__ __forceinline__ void cp_wait0() {
    asm volatile("cp.async.wait_group 0;" ::: "memory");
}

__device__ __forceinline__ void ldsm4(uint32_t& r0, uint32_t& r1, uint32_t& r2, uint32_t& r3,
                                      uint32_t a) {
    asm volatile("ldmatrix.sync.aligned.m8n8.x4.shared.b16 {%0,%1,%2,%3}, [%4];"
                 : "=r"(r0), "=r"(r1), "=r"(r2), "=r"(r3) : "r"(a));
}

__device__ __forceinline__ void mma16816(float* c, const uint32_t* a, uint32_t b0, uint32_t b1) {
    asm volatile(
        "mma.sync.aligned.m16n8k16.row.col.f32.f16.f16.f32 "
        "{%0,%1,%2,%3}, {%4,%5,%6,%7}, {%8,%9}, {%0,%1,%2,%3};"
        : "+f"(c[0]), "+f"(c[1]), "+f"(c[2]), "+f"(c[3])
        : "r"(a[0]), "r"(a[1]), "r"(a[2]), "r"(a[3]), "r"(b0), "r"(b1));
}

// ---------------- elementwise converts ---------------------------------------
__global__ void cast_kernel(const float* __restrict__ x, fp16* __restrict__ h)
{
    size_t i = ((size_t)blockIdx.x * 256 + threadIdx.x) * 4;
    float4 v = *(const float4*)(x + i);
    *(__half2*)(h + i)     = __floats2half2_rn(v.x, v.y);
    *(__half2*)(h + i + 2) = __floats2half2_rn(v.z, v.w);
}

__global__ void bias_concat(const float* __restrict__ expb,
                            const float* __restrict__ dsb1,
                            const float* __restrict__ rtb1,
                            float* __restrict__ big)
{
    int i = blockIdx.x * 256 + threadIdx.x;  // 0..5375
    float v;
    if (i < NE * HD)           v = expb[i];
    else if (i < NE * HD + HD) v = dsb1[i - NE * HD];
    else                       v = rtb1[i - NE * HD - HD];
    big[i] = v;
}

// ---------------- fp16 HMMA GEMM ---------------------------------------------
// C[M,N] = act( A[M,K] @ B[N,K]^T + bias ) * scale
// CTA tile 128x256, K-step 64, 8 warps (64x64 warp tiles), 4-stage cp.async,
// single __syncthreads per k-iter. gridDim.z=2 selects the (A2,B2,bias2)
// operand set with output-column offset colOff2 (used to fuse the two
// projections into one launch).
#define STAGE 49152u
#define SMEM_GEMM (4 * STAGE)

__device__ __forceinline__ void load_stage(
    uint32_t sb,
    const fp16* __restrict__ A, const fp16* __restrict__ B,
    int m0, int n0, int k0, int K, int t)
{
#pragma unroll
    for (int i = 0; i < 4; i++) {          // A: 128 rows x 8 chunks = 1024
        int id = t + (i << 8);
        int row = id >> 3, ch = id & 7;
        uint32_t off = (uint32_t)(row << 7) + (uint32_t)((ch ^ (row & 7)) << 4);
        cpasync16(sb + off, A + (size_t)(m0 + row) * K + k0 + (ch << 3));
    }
#pragma unroll
    for (int i = 0; i < 8; i++) {          // B: 256 rows x 8 chunks = 2048
        int id = t + (i << 8);
        int row = id >> 3, ch = id & 7;
        uint32_t off = (uint32_t)(row << 7) + (uint32_t)((ch ^ (row & 7)) << 4);
        cpasync16(sb + 16384 + off, B + (size_t)(n0 + row) * K + k0 + (ch << 3));
    }
}

__global__ void __launch_bounds__(256, 1)
gemm_tc(const fp16* __restrict__ A, const fp16* __restrict__ B,
        const float* __restrict__ bias,
        float* __restrict__ Cf, fp16* __restrict__ Ch,
        int K, int ldc, int act, const float* __restrict__ scale_ptr,
        const fp16* __restrict__ A2, const fp16* __restrict__ B2,
        const float* __restrict__ bias2, int colOff2)
{
    extern __shared__ __align__(128) char smem[];
    const uint32_t sb = smem_u32(smem);
    const int t = threadIdx.x;
    const int lane = t & 31, wid = t >> 5;
    const int wm = wid >> 2, wn = wid & 3;       // 2 x 4 warp grid
    const int m0 = blockIdx.y * 128;
    const int n0 = blockIdx.x * 256;
    int coff = 0;
    if (blockIdx.z) { A = A2; B = B2; bias = bias2; coff = colOff2; }

    float acc[4][8][4];
#pragma unroll
    for (int i = 0; i < 4; i++)
#pragma unroll
        for (int j = 0; j < 8; j++)
#pragma unroll
            for (int q = 0; q < 4; q++) acc[i][j][q] = 0.f;

    const int lm = lane >> 3, lr8 = lane & 7;
    const int a_rowoff = ((lm & 1) << 3) + lr8;
    const int a_choff  = (lm >> 1);
    const int b_rowoff = ((lm >> 1) << 3) + lr8;
    const int b_choff  = (lm & 1);

    const int iters = K >> 6;

    // prologue: fill 3 of 4 stages
    load_stage(sb, A, B, m0, n0, 0, K, t);
    cp_commit();
    if (iters > 1) { load_stage(sb + STAGE, A, B, m0, n0, 64, K, t); cp_commit(); }
    if (iters > 2) { load_stage(sb + 2 * STAGE, A, B, m0, n0, 128, K, t); cp_commit(); }

    for (int kt = 0; kt < iters; kt++) {
        // stage kt completion: groups committed after it so far = min(2, iters-1-kt)
        int after = iters - 1 - kt;
        if (after >= 2) cp_wait2();
        else if (after == 1) cp_wait1();
        else cp_wait0();
        // one barrier: (a) all threads' stage-kt loads visible,
        //              (b) all warps done computing iter kt-1 -> safe to overwrite (kt+3)%4
        __syncthreads();
        if (kt + 3 < iters) {
            load_stage(sb + (uint32_t)((kt + 3) & 3) * STAGE, A, B, m0, n0, (kt + 3) << 6, K, t);
            cp_commit();
        }

        const uint32_t ss = sb + (uint32_t)(kt & 3) * STAGE;
#pragma unroll 1
        for (int kk = 0; kk < 4; kk++) {
            uint32_t Af[4][4], Bf[4][4];
            const int chA = 2 * kk + a_choff;
            const int chB = 2 * kk + b_choff;
#pragma unroll
            for (int mi = 0; mi < 4; mi++) {
                int row = wm * 64 + mi * 16 + a_rowoff;
                uint32_t ad = ss + (row << 7) + (((chA ^ (row & 7))) << 4);
                ldsm4(Af[mi][0], Af[mi][1], Af[mi][2], Af[mi][3], ad);
            }
#pragma unroll
            for (int nj = 0; nj < 4; nj++) {
                int row = wn * 64 + nj * 16 + b_rowoff;
                uint32_t ad = ss + 16384 + (row << 7) + (((chB ^ (row & 7))) << 4);
                ldsm4(Bf[nj][0], Bf[nj][1], Bf[nj][2], Bf[nj][3], ad);
            }
#pragma unroll
            for (int mi = 0; mi < 4; mi++) {
#pragma unroll
                for (int nj = 0; nj < 4; nj++) {
                    mma16816(acc[mi][nj * 2],     Af[mi], Bf[nj][0], Bf[nj][1]);
                    mma16816(acc[mi][nj * 2 + 1], Af[mi], Bf[nj][2], Bf[nj][3]);
                }
            }
        }
    }

    // epilogue: direct stores from accumulators
    const float scale = scale_ptr ? expf(scale_ptr[0]) : 1.0f;
    const int lr = lane >> 2, lc = (lane & 3) * 2;
#pragma unroll
    for (int mi = 0; mi < 4; mi++) {
#pragma unroll
        for (int nj = 0; nj < 4; nj++) {
#pragma unroll
            for (int h = 0; h < 2; h++) {
                int col = n0 + wn * 64 + nj * 16 + h * 8 + lc;
                float bx = 0.f, by = 0.f;
                if (bias) { float2 bb = *(const float2*)(bias + col); bx = bb.x; by = bb.y; }
#pragma unroll
                for (int rh = 0; rh < 2; rh++) {
                    int row = m0 + wm * 64 + mi * 16 + rh * 8 + lr;
                    float v0 = acc[mi][nj * 2 + h][rh * 2 + 0] + bx;
                    float v1 = acc[mi][nj * 2 + h][rh * 2 + 1] + by;
                    if (act) { v0 = gelu_f(v0); v1 = gelu_f(v1); }
                    v0 *= scale; v1 *= scale;
                    size_t idx = (size_t)row * ldc + col + coff;
                    if (Cf) *(float2*)(Cf + idx) = make_float2(v0, v1);
                    if (Ch) *(__half2*)(Ch + idx) = __floats2half2_rn(v0, v1);
                }
            }
        }
    }
}

// ---------------- router: logits (4 x 256-dot) + softmax --------------------
// hid row: [expert 4096 | dsh 1024 | rth 256], fp16
__global__ void router_kernel(const fp16* __restrict__ hid,
                              const float* __restrict__ W2,
                              const float* __restrict__ b2,
                              float* __restrict__ probs_buf,
                              float* __restrict__ out_probs)
{
    int b = blockIdx.x;
    int lane = threadIdx.x & 31;
    int w = threadIdx.x >> 5;
    const fp16* x = hid + (size_t)b * NH + NE * HD + HD;
    const float* wr = W2 + (size_t)w * 256;
    float s = 0.f;
    for (int i = lane; i < 256; i += 32) s += __half2float(x[i]) * wr[i];
#pragma unroll
    for (int o = 16; o; o >>= 1) s += __shfl_xor_sync(0xffffffffu, s, o);
    __shared__ float sl[4];
    if (lane == 0) sl[w] = s + b2[w];
    __syncthreads();
    if (threadIdx.x == 0) {
        float m = fmaxf(fmaxf(sl[0], sl[1]), fmaxf(sl[2], sl[3]));
        float e[4]; float sum = 0.f;
#pragma unroll
        for (int i = 0; i < 4; i++) { e[i] = expf(sl[i] - m); sum += e[i]; }
        float inv = 1.f / sum;
#pragma unroll
        for (int i = 0; i < 4; i++) {
            float p = e[i] * inv;
            probs_buf[(size_t)b * 4 + i] = p;
            out_probs[(size_t)b * 4 + i] = p;
        }
    }
}

// ---------------- ds scalar + MoE mix (reads fused hid; emits fused fp16) ----
__global__ void fuse_kernel(const fp16* __restrict__ hid,
                            const float* __restrict__ dsW2,
                            const float* __restrict__ dsb2,
                            const float* __restrict__ probs,
                            fp16* __restrict__ fusedh,
                            float* __restrict__ ds_buf,
                            float* __restrict__ out_ds)
{
    int b = blockIdx.x;
    int t = threadIdx.x;  // 256
    const fp16* row = hid + (size_t)b * NH;
    const fp16* xr = row + NE * HD;          // dsh slice
    float s = 0.f;
    for (int k = t; k < HD; k += 256) s += __half2float(xr[k]) * dsW2[k];
    __shared__ float red[256];
    red[t] = s;
    __syncthreads();
    for (int off = 128; off; off >>= 1) {
        if (t < off) red[t] += red[t + off];
        __syncthreads();
    }
    if (t == 0) {
        float d = 1.f / (1.f + expf(-(red[0] + dsb2[0])));
        ds_buf[b] = d;
        out_ds[b] = d;
    }
    float p0 = probs[(size_t)b * 4 + 0], p1 = probs[(size_t)b * 4 + 1];
    float p2 = probs[(size_t)b * 4 + 2], p3 = probs[(size_t)b * 4 + 3];
    for (int h = t; h < HD; h += 256) {
        float v = p0 * __half2float(row[h])          + p1 * __half2float(row[HD + h])
                + p2 * __half2float(row[2 * HD + h]) + p3 * __half2float(row[3 * HD + h]);
        fusedh[(size_t)b * HD + h] = __float2half_rn(v);
    }
}

// ---------------- mix + L2 normalize, emit fp16 -------------------------------
__global__ void norm_kernel(const float* __restrict__ res,
                            const float* __restrict__ text,
                            const float* __restrict__ img,
                            const float* __restrict__ ds_buf,
                            const float* __restrict__ target,
                            fp16* __restrict__ predh,
                            fp16* __restrict__ tgth)
{
    int r = blockIdx.x;
    int t = threadIdx.x;  // 256, row length 768 = 3*256
    float o[3];
    fp16* dh;
    size_t base;
    if (r < B_SZ) {
        float d = ds_buf[r];
        base = (size_t)r * FD;
#pragma unroll
        for (int i = 0; i < 3; i++) {
            int j = t + i * 256;
            o[i] = d * text[base + j] + (1.0f - d) * img[base + j] + res[base + j];
        }
        dh = predh;
    } else {
        base = (size_t)(r - B_SZ) * FD;
#pragma unroll
        for (int i = 0; i < 3; i++) o[i] = target[base + t + i * 256];
        dh = tgth;
    }
    float s = o[0] * o[0] + o[1] * o[1] + o[2] * o[2];
    __shared__ float red[256];
    red[t] = s;
    __syncthreads();
    for (int off = 128; off; off >>= 1) {
        if (t < off) red[t] += red[t + off];
        __syncthreads();
    }
    __shared__ float inv_s;
    if (t == 0) inv_s = 1.0f / fmaxf(sqrtf(red[0]), 1e-12f);
    __syncthreads();
    float inv = inv_s;
#pragma unroll
    for (int i = 0; i < 3; i++)
        dh[base + t + i * 256] = __float2half_rn(o[i] * inv);
}

// ---------------- launch -----------------------------------------------------
#define SYM(var, sym) cudaGetSymbolAddress((void**)&var, sym)

extern "C" void kernel_launch(void* const* d_in, const int* in_sizes, int n_in,
                              void* d_out, int out_size)
{
    const float* img  = (const float*)d_in[0];
    const float* txt  = (const float*)d_in[1];
    const float* tgt  = (const float*)d_in[2];
    const float* Wt   = (const float*)d_in[3];
    const float* bt   = (const float*)d_in[4];
    const float* Wi   = (const float*)d_in[5];
    const float* bi   = (const float*)d_in[6];
    const float* dsW1 = (const float*)d_in[7];
    const float* dsb1 = (const float*)d_in[8];
    const float* dsW2 = (const float*)d_in[9];
    const float* dsb2 = (const float*)d_in[10];
    const float* expW = (const float*)d_in[11];
    const float* expb = (const float*)d_in[12];
    const float* rtW1 = (const float*)d_in[13];
    const float* rtb1 = (const float*)d_in[14];
    const float* rtW2 = (const float*)d_in[15];
    const float* rtb2 = (const float*)d_in[16];
    const float* outW = (const float*)d_in[17];
    const float* outb = (const float*)d_in[18];
    const float* lsc  = (const float*)d_in[19];

    float *probs, *ds, *res, *bigB;
    fp16 *hid;
    SYM(probs, g_probs); SYM(ds, g_ds); SYM(res, g_res);
    SYM(hid, g_hid); SYM(bigB, g_bigB);

    fp16 *txh, *imh, *cbh, *fuh, *prh, *tgh;
    fp16 *wth, *wih, *bigW, *owh;
    SYM(txh, g_txt_h); SYM(imh, g_img_h);
    SYM(cbh, g_comb_h); SYM(fuh, g_fused_h);
    SYM(prh, g_pred_h); SYM(tgh, g_tgt_h);
    SYM(wth, g_Wt_h); SYM(wih, g_Wi_h); SYM(bigW, g_bigW); SYM(owh, g_outW_h);

    float* out_logits = (float*)d_out;
    float* out_ds     = out_logits + (size_t)B_SZ * T_SZ;
    float* out_probs  = out_ds + B_SZ;

    cudaFuncSetAttribute(gemm_tc, cudaFuncAttributeMaxDynamicSharedMemorySize, SMEM_GEMM);

    // ---- casts: inputs + weights (fused weights into one buffer) ----
    cast_kernel<<<(B_SZ * FD) / 1024, 256>>>(txt, txh);
    cast_kernel<<<(B_SZ * FD) / 1024, 256>>>(img, imh);
    cast_kernel<<<(PD * FD) / 1024, 256>>>(Wt, wth);
    cast_kernel<<<(PD * FD) / 1024, 256>>>(Wi, wih);
    cast_kernel<<<(NE * HD * CB) / 1024, 256>>>(expW, bigW);
    cast_kernel<<<(HD * CB) / 1024, 256>>>(dsW1, bigW + (size_t)NE * HD * CB);
    cast_kernel<<<(256 * CB) / 1024, 256>>>(rtW1, bigW + (size_t)(NE * HD + HD) * CB);
    cast_kernel<<<(FD * HD) / 1024, 256>>>(outW, owh);
    bias_concat<<<NH / 256, 256>>>(expb, dsb1, rtb1, bigB);

    dim3 blk(256);
    // both projections in ONE launch (z=0: txt->cols 0:512, z=1: img->cols 512:1024)
    gemm_tc<<<dim3(PD / 256, B_SZ / 128, 2), blk, SMEM_GEMM>>>(
        txh, wth, bt, nullptr, cbh, FD, CB, 1, nullptr, imh, wih, bi, PD);

    // fused hidden GEMM: [B, 5376] = gelu(comb @ [expW|dsW1|rtW1]^T + bias)
    gemm_tc<<<dim3(NH / 256, B_SZ / 128, 1), blk, SMEM_GEMM>>>(
        cbh, bigW, bigB, nullptr, hid, CB, NH, 1, nullptr, nullptr, nullptr, nullptr, 0);

    // router softmax
    router_kernel<<<B_SZ, 128>>>(hid, rtW2, rtb2, probs, out_probs);

    // ds scalar + router-weighted expert mix -> fused fp16
    fuse_kernel<<<B_SZ, 256>>>(hid, dsW2, dsb2, probs, fuh, ds, out_ds);

    // residual [B, 768] f32
    gemm_tc<<<dim3(FD / 256, B_SZ / 128, 1), blk, SMEM_GEMM>>>(
        fuh, owh, outb, res, nullptr, HD, FD, 0, nullptr, nullptr, nullptr, nullptr, 0);

    // mix + normalize -> pred/tgt fp16
    norm_kernel<<<B_SZ + T_SZ, 256>>>(res, txt, img, ds, tgt, prh, tgh);

    // logits = exp(logit_scale) * pred @ tgt^T   [8192, 8192] f32
    gemm_tc<<<dim3(T_SZ / 256, B_SZ / 128, 1), blk, SMEM_GEMM>>>(
        prh, tgh, nullptr, out_logits, nullptr, FD, T_SZ, 0, lsc, nullptr, nullptr, nullptr, 0);
}

// round 10
// speedup vs baseline: 7.1501x; 1.0307x over previous
#include <cuda_runtime.h>
#include <cuda_fp16.h>
#include <math.h>
#include <stdint.h>

#define B_SZ 8192
#define T_SZ 8192
#define FD 768
#define PD 512
#define HD 1024
#define NE 4
#define CB 1024   // 2*P
#define NH 5376   // fused hidden: 4096 expert | 1024 ds | 256 router

typedef __half fp16;

// ---------------- scratch (device globals; no allocation allowed) ----------
__device__ float g_probs[(size_t)B_SZ * NE];
__device__ float g_ds[B_SZ];
__device__ float g_res[(size_t)B_SZ * FD];
__device__ fp16  g_hid[(size_t)B_SZ * NH];

__device__ __align__(256) fp16 g_txt_h[(size_t)B_SZ * FD];
__device__ __align__(256) fp16 g_img_h[(size_t)B_SZ * FD];
__device__ __align__(256) fp16 g_comb_h[(size_t)B_SZ * CB];
__device__ __align__(256) fp16 g_fused_h[(size_t)B_SZ * HD];
__device__ __align__(256) fp16 g_pred_h[(size_t)B_SZ * FD];
__device__ __align__(256) fp16 g_tgt_h[(size_t)T_SZ * FD];
__device__ __align__(256) fp16 g_Wt_h[(size_t)PD * FD];
__device__ __align__(256) fp16 g_Wi_h[(size_t)PD * FD];
__device__ __align__(256) fp16 g_bigW[(size_t)NH * CB];   // [expW | dsW1 | rtW1]
__device__ __align__(256) float g_bigB[NH];
__device__ __align__(256) fp16 g_outW_h[(size_t)FD * HD];

// ---------------- helpers ---------------------------------------------------
__device__ __forceinline__ float gelu_f(float x) {
    return 0.5f * x * (1.0f + erff(x * 0.70710678118654752440f));
}

__device__ __forceinline__ uint32_t smem_u32(const void* p) {
    uint32_t a;
    asm("{ .reg .u64 t; cvta.to.shared.u64 t, %1; cvt.u32.u64 %0, t; }" : "=r"(a) : "l"(p));
    return a;
}

__device__ __forceinline__ void cpasync16(uint32_t dst, const void* src) {
    asm volatile("cp.async.cg.shared.global [%0], [%1], 16;" :: "r"(dst), "l"(src));
}
__device__ __forceinline__ void cp_commit() {
    asm volatile("cp.async.commit_group;" ::: "memory");
}
__device__ __forceinline__ void cp_wait2() {
    asm volatile("cp.async.wait_group 2;" ::: "memory");
}
__device__ __forceinline__ void cp_wait1() {
    asm volatile("cp.async.wait_group 1;" ::: "memory");
}
__device__ __forceinline__ void cp_wait0() {
    asm volatile("cp.async.wait_group 0;" ::: "memory");
}

__device__ __forceinline__ void ldsm4(uint32_t& r0, uint32_t& r1, uint32_t& r2, uint32_t& r3,
                                      uint32_t a) {
    asm volatile("ldmatrix.sync.aligned.m8n8.x4.shared.b16 {%0,%1,%2,%3}, [%4];"
                 : "=r"(r0), "=r"(r1), "=r"(r2), "=r"(r3) : "r"(a));
}

__device__ __forceinline__ void mma16816(float* c, const uint32_t* a, uint32_t b0, uint32_t b1) {
    asm volatile(
        "mma.sync.aligned.m16n8k16.row.col.f32.f16.f16.f32 "
        "{%0,%1,%2,%3}, {%4,%5,%6,%7}, {%8,%9}, {%0,%1,%2,%3};"
        : "+f"(c[0]), "+f"(c[1]), "+f"(c[2]), "+f"(c[3])
        : "r"(a[0]), "r"(a[1]), "r"(a[2]), "r"(a[3]), "r"(b0), "r"(b1));
}

// ---------------- megacast: all f32->fp16 casts + bias concat in ONE launch --
#define NB_TXT  6144   // 8192*768/1024
#define NB_IMG  6144
#define NB_WT   384    // 512*768/1024
#define NB_WI   384
#define NB_EXPW 4096   // 4096*1024/1024
#define NB_DSW  1024
#define NB_RTW  256
#define NB_OUTW 768
#define NB_BIAS 6      // 5376 f32 (guarded)
#define NB_TOTAL (NB_TXT + NB_IMG + NB_WT + NB_WI + NB_EXPW + NB_DSW + NB_RTW + NB_OUTW + NB_BIAS)

__device__ __forceinline__ void cast4(const float* __restrict__ x, fp16* __restrict__ h,
                                      size_t i) {
    float4 v = *(const float4*)(x + i);
    *(__half2*)(h + i)     = __floats2half2_rn(v.x, v.y);
    *(__half2*)(h + i + 2) = __floats2half2_rn(v.z, v.w);
}

__global__ void megacast(const float* __restrict__ txt,  const float* __restrict__ img,
                         const float* __restrict__ Wt,   const float* __restrict__ Wi,
                         const float* __restrict__ expW, const float* __restrict__ dsW1,
                         const float* __restrict__ rtW1, const float* __restrict__ outW,
                         const float* __restrict__ expb, const float* __restrict__ dsb1,
                         const float* __restrict__ rtb1,
                         fp16* __restrict__ txh,  fp16* __restrict__ imh,
                         fp16* __restrict__ wth,  fp16* __restrict__ wih,
                         fp16* __restrict__ bigW, fp16* __restrict__ owh,
                         float* __restrict__ bigB)
{
    int b = blockIdx.x;
    if (b < NB_TXT) { cast4(txt, txh, ((size_t)b * 256 + threadIdx.x) * 4); return; }
    b -= NB_TXT;
    if (b < NB_IMG) { cast4(img, imh, ((size_t)b * 256 + threadIdx.x) * 4); return; }
    b -= NB_IMG;
    if (b < NB_WT)  { cast4(Wt, wth, ((size_t)b * 256 + threadIdx.x) * 4); return; }
    b -= NB_WT;
    if (b < NB_WI)  { cast4(Wi, wih, ((size_t)b * 256 + threadIdx.x) * 4); return; }
    b -= NB_WI;
    if (b < NB_EXPW) { cast4(expW, bigW, ((size_t)b * 256 + threadIdx.x) * 4); return; }
    b -= NB_EXPW;
    if (b < NB_DSW) {
        cast4(dsW1, bigW + (size_t)NE * HD * CB, ((size_t)b * 256 + threadIdx.x) * 4); return;
    }
    b -= NB_DSW;
    if (b < NB_RTW) {
        cast4(rtW1, bigW + (size_t)(NE * HD + HD) * CB, ((size_t)b * 256 + threadIdx.x) * 4); return;
    }
    b -= NB_RTW;
    if (b < NB_OUTW) { cast4(outW, owh, ((size_t)b * 256 + threadIdx.x) * 4); return; }
    b -= NB_OUTW;
    {   // bias concat: [expb 4096 | dsb1 1024 | rtb1 256] f32
        int i = b * 1024 + threadIdx.x * 4;
#pragma unroll
        for (int q = 0; q < 4; q++) {
            int j = i + q;
            if (j < NH) {
                float v;
                if (j < NE * HD)           v = expb[j];
                else if (j < NE * HD + HD) v = dsb1[j - NE * HD];
                else                       v = rtb1[j - NE * HD - HD];
                bigB[j] = v;
            }
        }
    }
}

// ---------------- fp16 HMMA GEMM ---------------------------------------------
// C[M,N] = act( A[M,K] @ B[N,K]^T + bias ) * scale
// CTA tile 128x256, K-step 64, 8 warps (64x64 warp tiles), 4-stage cp.async,
// single __syncthreads per k-iter, fully-unrolled kk loop.
#define STAGE 49152u
#define SMEM_GEMM (4 * STAGE)

__device__ __forceinline__ void load_stage(
    uint32_t sb,
    const fp16* __restrict__ A, const fp16* __restrict__ B,
    int m0, int n0, int k0, int K, int t)
{
#pragma unroll
    for (int i = 0; i < 4; i++) {          // A: 128 rows x 8 chunks = 1024
        int id = t + (i << 8);
        int row = id >> 3, ch = id & 7;
        uint32_t off = (uint32_t)(row << 7) + (uint32_t)((ch ^ (row & 7)) << 4);
        cpasync16(sb + off, A + (size_t)(m0 + row) * K + k0 + (ch << 3));
    }
#pragma unroll
    for (int i = 0; i < 8; i++) {          // B: 256 rows x 8 chunks = 2048
        int id = t + (i << 8);
        int row = id >> 3, ch = id & 7;
        uint32_t off = (uint32_t)(row << 7) + (uint32_t)((ch ^ (row & 7)) << 4);
        cpasync16(sb + 16384 + off, B + (size_t)(n0 + row) * K + k0 + (ch << 3));
    }
}

__global__ void __launch_bounds__(256, 1)
gemm_tc(const fp16* __restrict__ A, const fp16* __restrict__ B,
        const float* __restrict__ bias,
        float* __restrict__ Cf, fp16* __restrict__ Ch,
        int K, int ldc, int act, const float* __restrict__ scale_ptr,
        const fp16* __restrict__ A2, const fp16* __restrict__ B2,
        const float* __restrict__ bias2, int colOff2)
{
    extern __shared__ __align__(128) char smem[];
    const uint32_t sb = smem_u32(smem);
    const int t = threadIdx.x;
    const int lane = t & 31, wid = t >> 5;
    const int wm = wid >> 2, wn = wid & 3;       // 2 x 4 warp grid
    const int m0 = blockIdx.y * 128;
    const int n0 = blockIdx.x * 256;
    int coff = 0;
    if (blockIdx.z) { A = A2; B = B2; bias = bias2; coff = colOff2; }

    float acc[4][8][4];
#pragma unroll
    for (int i = 0; i < 4; i++)
#pragma unroll
        for (int j = 0; j < 8; j++)
#pragma unroll
            for (int q = 0; q < 4; q++) acc[i][j][q] = 0.f;

    const int lm = lane >> 3, lr8 = lane & 7;
    // precomputed per-lane row bases (swizzle row term + chunk parity)
    const int a_row  = wm * 64 + ((lm & 1) << 3) + lr8;   // + mi*16
    const int a_choff = (lm >> 1);
    const int b_row  = wn * 64 + ((lm >> 1) << 3) + lr8;  // + nj*16
    const int b_choff = (lm & 1);

    const int iters = K >> 6;

    // prologue: fill 3 of 4 stages
    load_stage(sb, A, B, m0, n0, 0, K, t);
    cp_commit();
    if (iters > 1) { load_stage(sb + STAGE, A, B, m0, n0, 64, K, t); cp_commit(); }
    if (iters > 2) { load_stage(sb + 2 * STAGE, A, B, m0, n0, 128, K, t); cp_commit(); }

    for (int kt = 0; kt < iters; kt++) {
        int after = iters - 1 - kt;
        if (after >= 2) cp_wait2();
        else if (after == 1) cp_wait1();
        else cp_wait0();
        __syncthreads();
        if (kt + 3 < iters) {
            load_stage(sb + (uint32_t)((kt + 3) & 3) * STAGE, A, B, m0, n0, (kt + 3) << 6, K, t);
            cp_commit();
        }

        const uint32_t ss = sb + (uint32_t)(kt & 3) * STAGE;
#pragma unroll
        for (int kk = 0; kk < 4; kk++) {
            uint32_t Af[4][4], Bf[4][4];
            const int chA = 2 * kk + a_choff;
            const int chB = 2 * kk + b_choff;
#pragma unroll
            for (int mi = 0; mi < 4; mi++) {
                int row = a_row + mi * 16;
                uint32_t ad = ss + (row << 7) + (((chA ^ (row & 7))) << 4);
                ldsm4(Af[mi][0], Af[mi][1], Af[mi][2], Af[mi][3], ad);
            }
#pragma unroll
            for (int nj = 0; nj < 4; nj++) {
                int row = b_row + nj * 16;
                uint32_t ad = ss + 16384 + (row << 7) + (((chB ^ (row & 7))) << 4);
                ldsm4(Bf[nj][0], Bf[nj][1], Bf[nj][2], Bf[nj][3], ad);
            }
#pragma unroll
            for (int mi = 0; mi < 4; mi++) {
#pragma unroll
                for (int nj = 0; nj < 4; nj++) {
                    mma16816(acc[mi][nj * 2],     Af[mi], Bf[nj][0], Bf[nj][1]);
                    mma16816(acc[mi][nj * 2 + 1], Af[mi], Bf[nj][2], Bf[nj][3]);
                }
            }
        }
    }

    // epilogue: direct stores from accumulators
    const float scale = scale_ptr ? expf(scale_ptr[0]) : 1.0f;
    const int lr = lane >> 2, lc = (lane & 3) * 2;
#pragma unroll
    for (int mi = 0; mi < 4; mi++) {
#pragma unroll
        for (int nj = 0; nj < 4; nj++) {
#pragma unroll
            for (int h = 0; h < 2; h++) {
                int col = n0 + wn * 64 + nj * 16 + h * 8 + lc;
                float bx = 0.f, by = 0.f;
                if (bias) { float2 bb = *(const float2*)(bias + col); bx = bb.x; by = bb.y; }
#pragma unroll
                for (int rh = 0; rh < 2; rh++) {
                    int row = m0 + wm * 64 + mi * 16 + rh * 8 + lr;
                    float v0 = acc[mi][nj * 2 + h][rh * 2 + 0] + bx;
                    float v1 = acc[mi][nj * 2 + h][rh * 2 + 1] + by;
                    if (act) { v0 = gelu_f(v0); v1 = gelu_f(v1); }
                    v0 *= scale; v1 *= scale;
                    size_t idx = (size_t)row * ldc + col + coff;
                    if (Cf) *(float2*)(Cf + idx) = make_float2(v0, v1);
                    if (Ch) *(__half2*)(Ch + idx) = __floats2half2_rn(v0, v1);
                }
            }
        }
    }
}

// ---------------- router: logits (4 x 256-dot) + softmax --------------------
__global__ void router_kernel(const fp16* __restrict__ hid,
                              const float* __restrict__ W2,
                              const float* __restrict__ b2,
                              float* __restrict__ probs_buf,
                              float* __restrict__ out_probs)
{
    int b = blockIdx.x;
    int lane = threadIdx.x & 31;
    int w = threadIdx.x >> 5;
    const fp16* x = hid + (size_t)b * NH + NE * HD + HD;
    const float* wr = W2 + (size_t)w * 256;
    float s = 0.f;
    for (int i = lane; i < 256; i += 32) s += __half2float(x[i]) * wr[i];
#pragma unroll
    for (int o = 16; o; o >>= 1) s += __shfl_xor_sync(0xffffffffu, s, o);
    __shared__ float sl[4];
    if (lane == 0) sl[w] = s + b2[w];
    __syncthreads();
    if (threadIdx.x == 0) {
        float m = fmaxf(fmaxf(sl[0], sl[1]), fmaxf(sl[2], sl[3]));
        float e[4]; float sum = 0.f;
#pragma unroll
        for (int i = 0; i < 4; i++) { e[i] = expf(sl[i] - m); sum += e[i]; }
        float inv = 1.f / sum;
#pragma unroll
        for (int i = 0; i < 4; i++) {
            float p = e[i] * inv;
            probs_buf[(size_t)b * 4 + i] = p;
            out_probs[(size_t)b * 4 + i] = p;
        }
    }
}

// ---------------- ds scalar + MoE mix ----------------------------------------
__global__ void fuse_kernel(const fp16* __restrict__ hid,
                            const float* __restrict__ dsW2,
                            const float* __restrict__ dsb2,
                            const float* __restrict__ probs,
                            fp16* __restrict__ fusedh,
                            float* __restrict__ ds_buf,
                            float* __restrict__ out_ds)
{
    int b = blockIdx.x;
    int t = threadIdx.x;  // 256
    const fp16* row = hid + (size_t)b * NH;
    const fp16* xr = row + NE * HD;
    float s = 0.f;
    for (int k = t; k < HD; k += 256) s += __half2float(xr[k]) * dsW2[k];
    __shared__ float red[256];
    red[t] = s;
    __syncthreads();
    for (int off = 128; off; off >>= 1) {
        if (t < off) red[t] += red[t + off];
        __syncthreads();
    }
    if (t == 0) {
        float d = 1.f / (1.f + expf(-(red[0] + dsb2[0])));
        ds_buf[b] = d;
        out_ds[b] = d;
    }
    float p0 = probs[(size_t)b * 4 + 0], p1 = probs[(size_t)b * 4 + 1];
    float p2 = probs[(size_t)b * 4 + 2], p3 = probs[(size_t)b * 4 + 3];
    for (int h = t; h < HD; h += 256) {
        float v = p0 * __half2float(row[h])          + p1 * __half2float(row[HD + h])
                + p2 * __half2float(row[2 * HD + h]) + p3 * __half2float(row[3 * HD + h]);
        fusedh[(size_t)b * HD + h] = __float2half_rn(v);
    }
}

// ---------------- mix + L2 normalize, emit fp16 -------------------------------
__global__ void norm_kernel(const float* __restrict__ res,
                            const float* __restrict__ text,
                            const float* __restrict__ img,
                            const float* __restrict__ ds_buf,
                            const float* __restrict__ target,
                            fp16* __restrict__ predh,
                            fp16* __restrict__ tgth)
{
    int r = blockIdx.x;
    int t = threadIdx.x;  // 256, row length 768 = 3*256
    float o[3];
    fp16* dh;
    size_t base;
    if (r < B_SZ) {
        float d = ds_buf[r];
        base = (size_t)r * FD;
#pragma unroll
        for (int i = 0; i < 3; i++) {
            int j = t + i * 256;
            o[i] = d * text[base + j] + (1.0f - d) * img[base + j] + res[base + j];
        }
        dh = predh;
    } else {
        base = (size_t)(r - B_SZ) * FD;
#pragma unroll
        for (int i = 0; i < 3; i++) o[i] = target[base + t + i * 256];
        dh = tgth;
    }
    float s = o[0] * o[0] + o[1] * o[1] + o[2] * o[2];
    __shared__ float red[256];
    red[t] = s;
    __syncthreads();
    for (int off = 128; off; off >>= 1) {
        if (t < off) red[t] += red[t + off];
        __syncthreads();
    }
    __shared__ float inv_s;
    if (t == 0) inv_s = 1.0f / fmaxf(sqrtf(red[0]), 1e-12f);
    __syncthreads();
    float inv = inv_s;
#pragma unroll
    for (int i = 0; i < 3; i++)
        dh[base + t + i * 256] = __float2half_rn(o[i] * inv);
}

// ---------------- launch -----------------------------------------------------
#define SYM(var, sym) cudaGetSymbolAddress((void**)&var, sym)

extern "C" void kernel_launch(void* const* d_in, const int* in_sizes, int n_in,
                              void* d_out, int out_size)
{
    const float* img  = (const float*)d_in[0];
    const float* txt  = (const float*)d_in[1];
    const float* tgt  = (const float*)d_in[2];
    const float* Wt   = (const float*)d_in[3];
    const float* bt   = (const float*)d_in[4];
    const float* Wi   = (const float*)d_in[5];
    const float* bi   = (const float*)d_in[6];
    const float* dsW1 = (const float*)d_in[7];
    const float* dsb1 = (const float*)d_in[8];
    const float* dsW2 = (const float*)d_in[9];
    const float* dsb2 = (const float*)d_in[10];
    const float* expW = (const float*)d_in[11];
    const float* expb = (const float*)d_in[12];
    const float* rtW1 = (const float*)d_in[13];
    const float* rtb1 = (const float*)d_in[14];
    const float* rtW2 = (const float*)d_in[15];
    const float* rtb2 = (const float*)d_in[16];
    const float* outW = (const float*)d_in[17];
    const float* outb = (const float*)d_in[18];
    const float* lsc  = (const float*)d_in[19];

    float *probs, *ds, *res, *bigB;
    fp16 *hid;
    SYM(probs, g_probs); SYM(ds, g_ds); SYM(res, g_res);
    SYM(hid, g_hid); SYM(bigB, g_bigB);

    fp16 *txh, *imh, *cbh, *fuh, *prh, *tgh;
    fp16 *wth, *wih, *bigW, *owh;
    SYM(txh, g_txt_h); SYM(imh, g_img_h);
    SYM(cbh, g_comb_h); SYM(fuh, g_fused_h);
    SYM(prh, g_pred_h); SYM(tgh, g_tgt_h);
    SYM(wth, g_Wt_h); SYM(wih, g_Wi_h); SYM(bigW, g_bigW); SYM(owh, g_outW_h);

    float* out_logits = (float*)d_out;
    float* out_ds     = out_logits + (size_t)B_SZ * T_SZ;
    float* out_probs  = out_ds + B_SZ;

    cudaFuncSetAttribute(gemm_tc, cudaFuncAttributeMaxDynamicSharedMemorySize, SMEM_GEMM);

    // (1) all casts + bias concat in one launch
    megacast<<<NB_TOTAL, 256>>>(txt, img, Wt, Wi, expW, dsW1, rtW1, outW,
                                expb, dsb1, rtb1,
                                txh, imh, wth, wih, bigW, owh, bigB);

    dim3 blk(256);
    // (2) both projections in ONE launch (z=0: txt->cols 0:512, z=1: img->cols 512:1024)
    gemm_tc<<<dim3(PD / 256, B_SZ / 128, 2), blk, SMEM_GEMM>>>(
        txh, wth, bt, nullptr, cbh, FD, CB, 1, nullptr, imh, wih, bi, PD);

    // (3) fused hidden GEMM: [B, 5376] = gelu(comb @ [expW|dsW1|rtW1]^T + bias)
    gemm_tc<<<dim3(NH / 256, B_SZ / 128, 1), blk, SMEM_GEMM>>>(
        cbh, bigW, bigB, nullptr, hid, CB, NH, 1, nullptr, nullptr, nullptr, nullptr, 0);

    // (4) router softmax
    router_kernel<<<B_SZ, 128>>>(hid, rtW2, rtb2, probs, out_probs);

    // (5) ds scalar + router-weighted expert mix -> fused fp16
    fuse_kernel<<<B_SZ, 256>>>(hid, dsW2, dsb2, probs, fuh, ds, out_ds);

    // (6) residual [B, 768] f32   <-- ncu -s 5 -c 1 profiles this launch
    gemm_tc<<<dim3(FD / 256, B_SZ / 128, 1), blk, SMEM_GEMM>>>(
        fuh, owh, outb, res, nullptr, HD, FD, 0, nullptr, nullptr, nullptr, nullptr, 0);

    // (7) mix + normalize -> pred/tgt fp16
    norm_kernel<<<B_SZ + T_SZ, 256>>>(res, txt, img, ds, tgt, prh, tgh);

    // (8) logits = exp(logit_scale) * pred @ tgt^T   [8192, 8192] f32
    gemm_tc<<<dim3(T_SZ / 256, B_SZ / 128, 1), blk, SMEM_GEMM>>>(
        prh, tgh, nullptr, out_logits, nullptr, FD, T_SZ, 0, lsc, nullptr, nullptr, nullptr, 0);
}

// round 12
// speedup vs baseline: 7.7619x; 1.0856x over previous
#include <cuda_runtime.h>
#include <cuda_fp16.h>
#include <math.h>
#include <stdint.h>

#define B_SZ 8192
#define T_SZ 8192
#define FD 768
#define PD 512
#define HD 1024
#define NE 4
#define CB 1024   // 2*P
#define NH 5376   // fused hidden: 4096 expert | 1024 ds | 256 router

typedef __half fp16;

// ---------------- scratch (device globals; no allocation allowed) ----------
__device__ float g_probs[(size_t)B_SZ * NE];
__device__ float g_ds[B_SZ];
__device__ float g_res[(size_t)B_SZ * FD];
__device__ fp16  g_hid[(size_t)B_SZ * NH];

__device__ __align__(256) fp16 g_txt_h[(size_t)B_SZ * FD];
__device__ __align__(256) fp16 g_img_h[(size_t)B_SZ * FD];
__device__ __align__(256) fp16 g_comb_h[(size_t)B_SZ * CB];
__device__ __align__(256) fp16 g_fused_h[(size_t)B_SZ * HD];
__device__ __align__(256) fp16 g_pred_h[(size_t)B_SZ * FD];
__device__ __align__(256) fp16 g_tgt_h[(size_t)T_SZ * FD];
__device__ __align__(256) fp16 g_Wt_h[(size_t)PD * FD];
__device__ __align__(256) fp16 g_Wi_h[(size_t)PD * FD];
__device__ __align__(256) fp16 g_bigW[(size_t)NH * CB];   // [expW | dsW1 | rtW1]
__device__ __align__(256) float g_bigB[NH];
__device__ __align__(256) fp16 g_outW_h[(size_t)FD * HD];

// ---------------- helpers ---------------------------------------------------
__device__ __forceinline__ float gelu_f(float x) {
    return 0.5f * x * (1.0f + erff(x * 0.70710678118654752440f));
}

__device__ __forceinline__ uint32_t smem_u32(const void* p) {
    uint32_t a;
    asm("{ .reg .u64 t; cvta.to.shared.u64 t, %1; cvt.u32.u64 %0, t; }" : "=r"(a) : "l"(p));
    return a;
}

__device__ __forceinline__ void cpasync16(uint32_t dst, const void* src) {
    asm volatile("cp.async.cg.shared.global [%0], [%1], 16;" :: "r"(dst), "l"(src));
}
__device__ __forceinline__ void cp_commit() {
    asm volatile("cp.async.commit_group;" ::: "memory");
}
__device__ __forceinline__ void cp_wait1() {
    asm volatile("cp.async.wait_group 1;" ::: "memory");
}
__device__ __forceinline__ void cp_wait0() {
    asm volatile("cp.async.wait_group 0;" ::: "memory");
}

__device__ __forceinline__ void ldsm4(uint32_t& r0, uint32_t& r1, uint32_t& r2, uint32_t& r3,
                                      uint32_t a) {
    asm volatile("ldmatrix.sync.aligned.m8n8.x4.shared.b16 {%0,%1,%2,%3}, [%4];"
                 : "=r"(r0), "=r"(r1), "=r"(r2), "=r"(r3) : "r"(a));
}

__device__ __forceinline__ void mma16816(float* c, const uint32_t* a, uint32_t b0, uint32_t b1) {
    asm volatile(
        "mma.sync.aligned.m16n8k16.row.col.f32.f16.f16.f32 "
        "{%0,%1,%2,%3}, {%4,%5,%6,%7}, {%8,%9}, {%0,%1,%2,%3};"
        : "+f"(c[0]), "+f"(c[1]), "+f"(c[2]), "+f"(c[3])
        : "r"(a[0]), "r"(a[1]), "r"(a[2]), "r"(a[3]), "r"(b0), "r"(b1));
}

// ---------------- megacast: all f32->fp16 casts + bias concat in ONE launch --
#define NB_TXT  6144
#define NB_IMG  6144
#define NB_WT   384
#define NB_WI   384
#define NB_EXPW 4096
#define NB_DSW  1024
#define NB_RTW  256
#define NB_OUTW 768
#define NB_BIAS 6
#define NB_TOTAL (NB_TXT + NB_IMG + NB_WT + NB_WI + NB_EXPW + NB_DSW + NB_RTW + NB_OUTW + NB_BIAS)

__device__ __forceinline__ void cast4(const float* __restrict__ x, fp16* __restrict__ h,
                                      size_t i) {
    float4 v = *(const float4*)(x + i);
    *(__half2*)(h + i)     = __floats2half2_rn(v.x, v.y);
    *(__half2*)(h + i + 2) = __floats2half2_rn(v.z, v.w);
}

__global__ void megacast(const float* __restrict__ txt,  const float* __restrict__ img,
                         const float* __restrict__ Wt,   const float* __restrict__ Wi,
                         const float* __restrict__ expW, const float* __restrict__ dsW1,
                         const float* __restrict__ rtW1, const float* __restrict__ outW,
                         const float* __restrict__ expb, const float* __restrict__ dsb1,
                         const float* __restrict__ rtb1,
                         fp16* __restrict__ txh,  fp16* __restrict__ imh,
                         fp16* __restrict__ wth,  fp16* __restrict__ wih,
                         fp16* __restrict__ bigW, fp16* __restrict__ owh,
                         float* __restrict__ bigB)
{
    int b = blockIdx.x;
    if (b < NB_TXT) { cast4(txt, txh, ((size_t)b * 256 + threadIdx.x) * 4); return; }
    b -= NB_TXT;
    if (b < NB_IMG) { cast4(img, imh, ((size_t)b * 256 + threadIdx.x) * 4); return; }
    b -= NB_IMG;
    if (b < NB_WT)  { cast4(Wt, wth, ((size_t)b * 256 + threadIdx.x) * 4); return; }
    b -= NB_WT;
    if (b < NB_WI)  { cast4(Wi, wih, ((size_t)b * 256 + threadIdx.x) * 4); return; }
    b -= NB_WI;
    if (b < NB_EXPW) { cast4(expW, bigW, ((size_t)b * 256 + threadIdx.x) * 4); return; }
    b -= NB_EXPW;
    if (b < NB_DSW) {
        cast4(dsW1, bigW + (size_t)NE * HD * CB, ((size_t)b * 256 + threadIdx.x) * 4); return;
    }
    b -= NB_DSW;
    if (b < NB_RTW) {
        cast4(rtW1, bigW + (size_t)(NE * HD + HD) * CB, ((size_t)b * 256 + threadIdx.x) * 4); return;
    }
    b -= NB_RTW;
    if (b < NB_OUTW) { cast4(outW, owh, ((size_t)b * 256 + threadIdx.x) * 4); return; }
    b -= NB_OUTW;
    {   // bias concat: [expb 4096 | dsb1 1024 | rtb1 256] f32
        int i = b * 1024 + threadIdx.x * 4;
#pragma unroll
        for (int q = 0; q < 4; q++) {
            int j = i + q;
            if (j < NH) {
                float v;
                if (j < NE * HD)           v = expb[j];
                else if (j < NE * HD + HD) v = dsb1[j - NE * HD];
                else                       v = rtb1[j - NE * HD - HD];
                bigB[j] = v;
            }
        }
    }
}

// ---------------- fp16 HMMA GEMM ---------------------------------------------
// C[M,N] = act( A[M,K] @ B[N,K]^T + bias ) * scale
// CTA tile 128x128, K-step 64, 4 warps (2x2, 64x64 warp tiles), 3-stage
// cp.async, single __syncthreads per k-iter, 2 CTAs/SM for cross-CTA overlap.
// Stage layout: A @0 (16K), B @16384 (16K). STAGE = 32K, 3 stages = 96K/CTA.
#define STAGE 32768u
#define SMEM_GEMM (3 * STAGE)

__device__ __forceinline__ void load_stage(
    uint32_t sb,
    const fp16* __restrict__ A, const fp16* __restrict__ B,
    int m0, int n0, int k0, int K, int t)
{
#pragma unroll
    for (int i = 0; i < 8; i++) {          // A: 128 rows x 8 chunks = 1024
        int id = t + (i << 7);
        int row = id >> 3, ch = id & 7;
        uint32_t off = (uint32_t)(row << 7) + (uint32_t)((ch ^ (row & 7)) << 4);
        cpasync16(sb + off, A + (size_t)(m0 + row) * K + k0 + (ch << 3));
    }
#pragma unroll
    for (int i = 0; i < 8; i++) {          // B: 128 rows x 8 chunks = 1024
        int id = t + (i << 7);
        int row = id >> 3, ch = id & 7;
        uint32_t off = (uint32_t)(row << 7) + (uint32_t)((ch ^ (row & 7)) << 4);
        cpasync16(sb + 16384 + off, B + (size_t)(n0 + row) * K + k0 + (ch << 3));
    }
}

__global__ void __launch_bounds__(128, 2)
gemm_tc(const fp16* __restrict__ A, const fp16* __restrict__ B,
        const float* __restrict__ bias,
        float* __restrict__ Cf, fp16* __restrict__ Ch,
        int K, int ldc, int act, const float* __restrict__ scale_ptr,
        const fp16* __restrict__ A2, const fp16* __restrict__ B2,
        const float* __restrict__ bias2, int colOff2)
{
    extern __shared__ __align__(128) char smem[];
    const uint32_t sb = smem_u32(smem);
    const int t = threadIdx.x;
    const int lane = t & 31, wid = t >> 5;
    const int wm = wid >> 1, wn = wid & 1;       // 2 x 2 warp grid, 64x64 tiles
    const int m0 = blockIdx.y * 128;
    const int n0 = blockIdx.x * 128;
    int coff = 0;
    if (blockIdx.z) { A = A2; B = B2; bias = bias2; coff = colOff2; }

    float acc[4][8][4];
#pragma unroll
    for (int i = 0; i < 4; i++)
#pragma unroll
        for (int j = 0; j < 8; j++)
#pragma unroll
            for (int q = 0; q < 4; q++) acc[i][j][q] = 0.f;

    const int lm = lane >> 3, lr8 = lane & 7;
    const int a_row  = wm * 64 + ((lm & 1) << 3) + lr8;   // + mi*16
    const int a_choff = (lm >> 1);
    const int b_row  = wn * 64 + ((lm >> 1) << 3) + lr8;  // + nj*16
    const int b_choff = (lm & 1);

    const int iters = K >> 6;

    // prologue: fill 2 of 3 stages
    load_stage(sb, A, B, m0, n0, 0, K, t);
    cp_commit();
    if (iters > 1) { load_stage(sb + STAGE, A, B, m0, n0, 64, K, t); cp_commit(); }

    for (int kt = 0; kt < iters; kt++) {
        // outstanding loads at top of iter kt: {kt, kt+1}; need kt complete
        if (kt + 1 < iters) cp_wait1();
        else cp_wait0();
        // single barrier: stage kt visible to all; compute kt-1 done by all
        // -> buffer (kt+2)%3 (== (kt-1)%3) free for the next load
        __syncthreads();
        if (kt + 2 < iters) {
            load_stage(sb + (uint32_t)((kt + 2) % 3) * STAGE, A, B, m0, n0, (kt + 2) << 6, K, t);
            cp_commit();
        }

        const uint32_t ss = sb + (uint32_t)(kt % 3) * STAGE;
#pragma unroll
        for (int kk = 0; kk < 4; kk++) {
            uint32_t Af[4][4], Bf[4][4];
            const int chA = 2 * kk + a_choff;
            const int chB = 2 * kk + b_choff;
#pragma unroll
            for (int mi = 0; mi < 4; mi++) {
                int row = a_row + mi * 16;
                uint32_t ad = ss + (row << 7) + (((chA ^ (row & 7))) << 4);
                ldsm4(Af[mi][0], Af[mi][1], Af[mi][2], Af[mi][3], ad);
            }
#pragma unroll
            for (int nj = 0; nj < 4; nj++) {
                int row = b_row + nj * 16;
                uint32_t ad = ss + 16384 + (row << 7) + (((chB ^ (row & 7))) << 4);
                ldsm4(Bf[nj][0], Bf[nj][1], Bf[nj][2], Bf[nj][3], ad);
            }
#pragma unroll
            for (int mi = 0; mi < 4; mi++) {
#pragma unroll
                for (int nj = 0; nj < 4; nj++) {
                    mma16816(acc[mi][nj * 2],     Af[mi], Bf[nj][0], Bf[nj][1]);
                    mma16816(acc[mi][nj * 2 + 1], Af[mi], Bf[nj][2], Bf[nj][3]);
                }
            }
        }
    }

    // epilogue: direct stores from accumulators
    const float scale = scale_ptr ? expf(scale_ptr[0]) : 1.0f;
    const int lr = lane >> 2, lc = (lane & 3) * 2;
#pragma unroll
    for (int mi = 0; mi < 4; mi++) {
#pragma unroll
        for (int nj = 0; nj < 4; nj++) {
#pragma unroll
            for (int h = 0; h < 2; h++) {
                int col = n0 + wn * 64 + nj * 16 + h * 8 + lc;
                float bx = 0.f, by = 0.f;
                if (bias) { float2 bb = *(const float2*)(bias + col); bx = bb.x; by = bb.y; }
#pragma unroll
                for (int rh = 0; rh < 2; rh++) {
                    int row = m0 + wm * 64 + mi * 16 + rh * 8 + lr;
                    float v0 = acc[mi][nj * 2 + h][rh * 2 + 0] + bx;
                    float v1 = acc[mi][nj * 2 + h][rh * 2 + 1] + by;
                    if (act) { v0 = gelu_f(v0); v1 = gelu_f(v1); }
                    v0 *= scale; v1 *= scale;
                    size_t idx = (size_t)row * ldc + col + coff;
                    if (Cf) *(float2*)(Cf + idx) = make_float2(v0, v1);
                    if (Ch) *(__half2*)(Ch + idx) = __floats2half2_rn(v0, v1);
                }
            }
        }
    }
}

// ---------------- router: logits (4 x 256-dot) + softmax --------------------
__global__ void router_kernel(const fp16* __restrict__ hid,
                              const float* __restrict__ W2,
                              const float* __restrict__ b2,
                              float* __restrict__ probs_buf,
                              float* __restrict__ out_probs)
{
    int b = blockIdx.x;
    int lane = threadIdx.x & 31;
    int w = threadIdx.x >> 5;
    const fp16* x = hid + (size_t)b * NH + NE * HD + HD;
    const float* wr = W2 + (size_t)w * 256;
    float s = 0.f;
    for (int i = lane; i < 256; i += 32) s += __half2float(x[i]) * wr[i];
#pragma unroll
    for (int o = 16; o; o >>= 1) s += __shfl_xor_sync(0xffffffffu, s, o);
    __shared__ float sl[4];
    if (lane == 0) sl[w] = s + b2[w];
    __syncthreads();
    if (threadIdx.x == 0) {
        float m = fmaxf(fmaxf(sl[0], sl[1]), fmaxf(sl[2], sl[3]));
        float e[4]; float sum = 0.f;
#pragma unroll
        for (int i = 0; i < 4; i++) { e[i] = expf(sl[i] - m); sum += e[i]; }
        float inv = 1.f / sum;
#pragma unroll
        for (int i = 0; i < 4; i++) {
            float p = e[i] * inv;
            probs_buf[(size_t)b * 4 + i] = p;
            out_probs[(size_t)b * 4 + i] = p;
        }
    }
}

// ---------------- ds scalar + MoE mix ----------------------------------------
__global__ void fuse_kernel(const fp16* __restrict__ hid,
                            const float* __restrict__ dsW2,
                            const float* __restrict__ dsb2,
                            const float* __restrict__ probs,
                            fp16* __restrict__ fusedh,
                            float* __restrict__ ds_buf,
                            float* __restrict__ out_ds)
{
    int b = blockIdx.x;
    int t = threadIdx.x;  // 256
    const fp16* row = hid + (size_t)b * NH;
    const fp16* xr = row + NE * HD;
    float s = 0.f;
    for (int k = t; k < HD; k += 256) s += __half2float(xr[k]) * dsW2[k];
    __shared__ float red[256];
    red[t] = s;
    __syncthreads();
    for (int off = 128; off; off >>= 1) {
        if (t < off) red[t] += red[t + off];
        __syncthreads();
    }
    if (t == 0) {
        float d = 1.f / (1.f + expf(-(red[0] + dsb2[0])));
        ds_buf[b] = d;
        out_ds[b] = d;
    }
    float p0 = probs[(size_t)b * 4 + 0], p1 = probs[(size_t)b * 4 + 1];
    float p2 = probs[(size_t)b * 4 + 2], p3 = probs[(size_t)b * 4 + 3];
    for (int h = t; h < HD; h += 256) {
        float v = p0 * __half2float(row[h])          + p1 * __half2float(row[HD + h])
                + p2 * __half2float(row[2 * HD + h]) + p3 * __half2float(row[3 * HD + h]);
        fusedh[(size_t)b * HD + h] = __float2half_rn(v);
    }
}

// ---------------- mix + L2 normalize, emit fp16 -------------------------------
__global__ void norm_kernel(const float* __restrict__ res,
                            const float* __restrict__ text,
                            const float* __restrict__ img,
                            const float* __restrict__ ds_buf,
                            const float* __restrict__ target,
                            fp16* __restrict__ predh,
                            fp16* __restrict__ tgth)
{
    int r = blockIdx.x;
    int t = threadIdx.x;  // 256, row length 768 = 3*256
    float o[3];
    fp16* dh;
    size_t base;
    if (r < B_SZ) {
        float d = ds_buf[r];
        base = (size_t)r * FD;
#pragma unroll
        for (int i = 0; i < 3; i++) {
            int j = t + i * 256;
            o[i] = d * text[base + j] + (1.0f - d) * img[base + j] + res[base + j];
        }
        dh = predh;
    } else {
        base = (size_t)(r - B_SZ) * FD;
#pragma unroll
        for (int i = 0; i < 3; i++) o[i] = target[base + t + i * 256];
        dh = tgth;
    }
    float s = o[0] * o[0] + o[1] * o[1] + o[2] * o[2];
    __shared__ float red[256];
    red[t] = s;
    __syncthreads();
    for (int off = 128; off; off >>= 1) {
        if (t < off) red[t] += red[t + off];
        __syncthreads();
    }
    __shared__ float inv_s;
    if (t == 0) inv_s = 1.0f / fmaxf(sqrtf(red[0]), 1e-12f);
    __syncthreads();
    float inv = inv_s;
#pragma unroll
    for (int i = 0; i < 3; i++)
        dh[base + t + i * 256] = __float2half_rn(o[i] * inv);
}

// ---------------- launch -----------------------------------------------------
#define SYM(var, sym) cudaGetSymbolAddress((void**)&var, sym)

extern "C" void kernel_launch(void* const* d_in, const int* in_sizes, int n_in,
                              void* d_out, int out_size)
{
    const float* img  = (const float*)d_in[0];
    const float* txt  = (const float*)d_in[1];
    const float* tgt  = (const float*)d_in[2];
    const float* Wt   = (const float*)d_in[3];
    const float* bt   = (const float*)d_in[4];
    const float* Wi   = (const float*)d_in[5];
    const float* bi   = (const float*)d_in[6];
    const float* dsW1 = (const float*)d_in[7];
    const float* dsb1 = (const float*)d_in[8];
    const float* dsW2 = (const float*)d_in[9];
    const float* dsb2 = (const float*)d_in[10];
    const float* expW = (const float*)d_in[11];
    const float* expb = (const float*)d_in[12];
    const float* rtW1 = (const float*)d_in[13];
    const float* rtb1 = (const float*)d_in[14];
    const float* rtW2 = (const float*)d_in[15];
    const float* rtb2 = (const float*)d_in[16];
    const float* outW = (const float*)d_in[17];
    const float* outb = (const float*)d_in[18];
    const float* lsc  = (const float*)d_in[19];

    float *probs, *ds, *res, *bigB;
    fp16 *hid;
    SYM(probs, g_probs); SYM(ds, g_ds); SYM(res, g_res);
    SYM(hid, g_hid); SYM(bigB, g_bigB);

    fp16 *txh, *imh, *cbh, *fuh, *prh, *tgh;
    fp16 *wth, *wih, *bigW, *owh;
    SYM(txh, g_txt_h); SYM(imh, g_img_h);
    SYM(cbh, g_comb_h); SYM(fuh, g_fused_h);
    SYM(prh, g_pred_h); SYM(tgh, g_tgt_h);
    SYM(wth, g_Wt_h); SYM(wih, g_Wi_h); SYM(bigW, g_bigW); SYM(owh, g_outW_h);

    float* out_logits = (float*)d_out;
    float* out_ds     = out_logits + (size_t)B_SZ * T_SZ;
    float* out_probs  = out_ds + B_SZ;

    cudaFuncSetAttribute(gemm_tc, cudaFuncAttributeMaxDynamicSharedMemorySize, SMEM_GEMM);

    // (1) all casts + bias concat in one launch
    megacast<<<NB_TOTAL, 256>>>(txt, img, Wt, Wi, expW, dsW1, rtW1, outW,
                                expb, dsb1, rtb1,
                                txh, imh, wth, wih, bigW, owh, bigB);

    dim3 blk(128);
    // (2) both projections in ONE launch (z=0: txt->cols 0:512, z=1: img->cols 512:1024)
    gemm_tc<<<dim3(PD / 128, B_SZ / 128, 2), blk, SMEM_GEMM>>>(
        txh, wth, bt, nullptr, cbh, FD, CB, 1, nullptr, imh, wih, bi, PD);

    // (3) fused hidden GEMM: [B, 5376] = gelu(comb @ [expW|dsW1|rtW1]^T + bias)
    gemm_tc<<<dim3(NH / 128, B_SZ / 128, 1), blk, SMEM_GEMM>>>(
        cbh, bigW, bigB, nullptr, hid, CB, NH, 1, nullptr, nullptr, nullptr, nullptr, 0);

    // (4) router softmax
    router_kernel<<<B_SZ, 128>>>(hid, rtW2, rtb2, probs, out_probs);

    // (5) ds scalar + router-weighted expert mix -> fused fp16
    fuse_kernel<<<B_SZ, 256>>>(hid, dsW2, dsb2, probs, fuh, ds, out_ds);

    // (6) residual [B, 768] f32
    gemm_tc<<<dim3(FD / 128, B_SZ / 128, 1), blk, SMEM_GEMM>>>(
        fuh, owh, outb, res, nullptr, HD, FD, 0, nullptr, nullptr, nullptr, nullptr, 0);

    // (7) mix + normalize -> pred/tgt fp16
    norm_kernel<<<B_SZ + T_SZ, 256>>>(res, txt, img, ds, tgt, prh, tgh);

    // (8) logits = exp(logit_scale) * pred @ tgt^T   [8192, 8192] f32
    gemm_tc<<<dim3(T_SZ / 128, B_SZ / 128, 1), blk, SMEM_GEMM>>>(
        prh, tgh, nullptr, out_logits, nullptr, FD, T_SZ, 0, lsc, nullptr, nullptr, nullptr, 0);
}

// round 14
// speedup vs baseline: 7.9721x; 1.0271x over previous
#include <cuda_runtime.h>
#include <cuda_fp16.h>
#include <math.h>
#include <stdint.h>

#define B_SZ 8192
#define T_SZ 8192
#define FD 768
#define PD 512
#define HD 1024
#define NE 4
#define CB 1024   // 2*P
#define NH 5376   // fused hidden: 4096 expert | 1024 ds | 256 router

typedef __half fp16;

// ---------------- scratch (device globals; no allocation allowed) ----------
__device__ float g_ds[B_SZ];
__device__ fp16  g_res[(size_t)B_SZ * FD];
__device__ fp16  g_hid[(size_t)B_SZ * NH];

__device__ __align__(256) fp16 g_txt_h[(size_t)B_SZ * FD];
__device__ __align__(256) fp16 g_img_h[(size_t)B_SZ * FD];
__device__ __align__(256) fp16 g_comb_h[(size_t)B_SZ * CB];
__device__ __align__(256) fp16 g_fused_h[(size_t)B_SZ * HD];
__device__ __align__(256) fp16 g_pred_h[(size_t)B_SZ * FD];
__device__ __align__(256) fp16 g_tgt_h[(size_t)T_SZ * FD];
__device__ __align__(256) fp16 g_Wt_h[(size_t)PD * FD];
__device__ __align__(256) fp16 g_Wi_h[(size_t)PD * FD];
__device__ __align__(256) fp16 g_bigW[(size_t)NH * CB];   // [expW | dsW1 | rtW1]
__device__ __align__(256) float g_bigB[NH];
__device__ __align__(256) fp16 g_outW_h[(size_t)FD * HD];

// ---------------- helpers ---------------------------------------------------
__device__ __forceinline__ float gelu_f(float x) {
    return 0.5f * x * (1.0f + erff(x * 0.70710678118654752440f));
}

__device__ __forceinline__ uint32_t smem_u32(const void* p) {
    uint32_t a;
    asm("{ .reg .u64 t; cvta.to.shared.u64 t, %1; cvt.u32.u64 %0, t; }" : "=r"(a) : "l"(p));
    return a;
}

__device__ __forceinline__ void cpasync16(uint32_t dst, const void* src) {
    asm volatile("cp.async.cg.shared.global [%0], [%1], 16;" :: "r"(dst), "l"(src));
}
__device__ __forceinline__ void cp_commit() {
    asm volatile("cp.async.commit_group;" ::: "memory");
}
__device__ __forceinline__ void cp_wait1() {
    asm volatile("cp.async.wait_group 1;" ::: "memory");
}
__device__ __forceinline__ void cp_wait0() {
    asm volatile("cp.async.wait_group 0;" ::: "memory");
}

__device__ __forceinline__ void ldsm4(uint32_t& r0, uint32_t& r1, uint32_t& r2, uint32_t& r3,
                                      uint32_t a) {
    asm volatile("ldmatrix.sync.aligned.m8n8.x4.shared.b16 {%0,%1,%2,%3}, [%4];"
                 : "=r"(r0), "=r"(r1), "=r"(r2), "=r"(r3) : "r"(a));
}

__device__ __forceinline__ void mma16816(float* c, const uint32_t* a, uint32_t b0, uint32_t b1) {
    asm volatile(
        "mma.sync.aligned.m16n8k16.row.col.f32.f16.f16.f32 "
        "{%0,%1,%2,%3}, {%4,%5,%6,%7}, {%8,%9}, {%0,%1,%2,%3};"
        : "+f"(c[0]), "+f"(c[1]), "+f"(c[2]), "+f"(c[3])
        : "r"(a[0]), "r"(a[1]), "r"(a[2]), "r"(a[3]), "r"(b0), "r"(b1));
}

// ---------------- megacast: all f32->fp16 casts + bias concat, 2048 elem/CTA -
#define NB_TXT  3072   // 8192*768/2048
#define NB_IMG  3072
#define NB_WT   192
#define NB_WI   192
#define NB_EXPW 2048
#define NB_DSW  512
#define NB_RTW  128
#define NB_OUTW 384
#define NB_BIAS 3      // 5376 f32 (guarded)
#define NB_TOTAL (NB_TXT + NB_IMG + NB_WT + NB_WI + NB_EXPW + NB_DSW + NB_RTW + NB_OUTW + NB_BIAS)

__device__ __forceinline__ uint32_t pack2(float a, float b) {
    __half2 h = __floats2half2_rn(a, b);
    return *(uint32_t*)&h;
}

__device__ __forceinline__ void cast8(const float* __restrict__ x, fp16* __restrict__ h,
                                      size_t i) {
    float4 v0 = *(const float4*)(x + i);
    float4 v1 = *(const float4*)(x + i + 4);
    uint4 o;
    o.x = pack2(v0.x, v0.y); o.y = pack2(v0.z, v0.w);
    o.z = pack2(v1.x, v1.y); o.w = pack2(v1.z, v1.w);
    *(uint4*)(h + i) = o;
}

__global__ void megacast(const float* __restrict__ txt,  const float* __restrict__ img,
                         const float* __restrict__ Wt,   const float* __restrict__ Wi,
                         const float* __restrict__ expW, const float* __restrict__ dsW1,
                         const float* __restrict__ rtW1, const float* __restrict__ outW,
                         const float* __restrict__ expb, const float* __restrict__ dsb1,
                         const float* __restrict__ rtb1,
                         fp16* __restrict__ txh,  fp16* __restrict__ imh,
                         fp16* __restrict__ wth,  fp16* __restrict__ wih,
                         fp16* __restrict__ bigW, fp16* __restrict__ owh,
                         float* __restrict__ bigB)
{
    int b = blockIdx.x;
    if (b < NB_TXT) { cast8(txt, txh, ((size_t)b * 256 + threadIdx.x) * 8); return; }
    b -= NB_TXT;
    if (b < NB_IMG) { cast8(img, imh, ((size_t)b * 256 + threadIdx.x) * 8); return; }
    b -= NB_IMG;
    if (b < NB_WT)  { cast8(Wt, wth, ((size_t)b * 256 + threadIdx.x) * 8); return; }
    b -= NB_WT;
    if (b < NB_WI)  { cast8(Wi, wih, ((size_t)b * 256 + threadIdx.x) * 8); return; }
    b -= NB_WI;
    if (b < NB_EXPW) { cast8(expW, bigW, ((size_t)b * 256 + threadIdx.x) * 8); return; }
    b -= NB_EXPW;
    if (b < NB_DSW) {
        cast8(dsW1, bigW + (size_t)NE * HD * CB, ((size_t)b * 256 + threadIdx.x) * 8); return;
    }
    b -= NB_DSW;
    if (b < NB_RTW) {
        cast8(rtW1, bigW + (size_t)(NE * HD + HD) * CB, ((size_t)b * 256 + threadIdx.x) * 8); return;
    }
    b -= NB_RTW;
    if (b < NB_OUTW) { cast8(outW, owh, ((size_t)b * 256 + threadIdx.x) * 8); return; }
    b -= NB_OUTW;
    {   // bias concat: [expb 4096 | dsb1 1024 | rtb1 256] f32
        int i = b * 2048 + threadIdx.x * 8;
#pragma unroll
        for (int q = 0; q < 8; q++) {
            int j = i + q;
            if (j < NH) {
                float v;
                if (j < NE * HD)           v = expb[j];
                else if (j < NE * HD + HD) v = dsb1[j - NE * HD];
                else                       v = rtb1[j - NE * HD - HD];
                bigB[j] = v;
            }
        }
    }
}

// ---------------- fp16 HMMA GEMM ---------------------------------------------
// C[M,N] = act( A[M,K] @ B[N,K]^T + bias ) * scale
// CTA tile 128x128, K-step 64, 4 warps (2x2, 64x64 warp tiles), 3-stage
// cp.async, single __syncthreads per k-iter, 2 CTAs/SM.
#define STAGE 32768u
#define SMEM_GEMM (3 * STAGE)

__device__ __forceinline__ void load_stage(
    uint32_t sb,
    const fp16* __restrict__ A, const fp16* __restrict__ B,
    int m0, int n0, int k0, int K, int t)
{
#pragma unroll
    for (int i = 0; i < 8; i++) {          // A: 128 rows x 8 chunks = 1024
        int id = t + (i << 7);
        int row = id >> 3, ch = id & 7;
        uint32_t off = (uint32_t)(row << 7) + (uint32_t)((ch ^ (row & 7)) << 4);
        cpasync16(sb + off, A + (size_t)(m0 + row) * K + k0 + (ch << 3));
    }
#pragma unroll
    for (int i = 0; i < 8; i++) {          // B: 128 rows x 8 chunks = 1024
        int id = t + (i << 7);
        int row = id >> 3, ch = id & 7;
        uint32_t off = (uint32_t)(row << 7) + (uint32_t)((ch ^ (row & 7)) << 4);
        cpasync16(sb + 16384 + off, B + (size_t)(n0 + row) * K + k0 + (ch << 3));
    }
}

__global__ void __launch_bounds__(128, 2)
gemm_tc(const fp16* __restrict__ A, const fp16* __restrict__ B,
        const float* __restrict__ bias,
        float* __restrict__ Cf, fp16* __restrict__ Ch,
        int K, int ldc, int act, const float* __restrict__ scale_ptr,
        const fp16* __restrict__ A2, const fp16* __restrict__ B2,
        const float* __restrict__ bias2, int colOff2)
{
    extern __shared__ __align__(128) char smem[];
    const uint32_t sb = smem_u32(smem);
    const int t = threadIdx.x;
    const int lane = t & 31, wid = t >> 5;
    const int wm = wid >> 1, wn = wid & 1;       // 2 x 2 warp grid, 64x64 tiles
    const int m0 = blockIdx.y * 128;
    const int n0 = blockIdx.x * 128;
    int coff = 0;
    if (blockIdx.z) { A = A2; B = B2; bias = bias2; coff = colOff2; }

    float acc[4][8][4];
#pragma unroll
    for (int i = 0; i < 4; i++)
#pragma unroll
        for (int j = 0; j < 8; j++)
#pragma unroll
            for (int q = 0; q < 4; q++) acc[i][j][q] = 0.f;

    const int lm = lane >> 3, lr8 = lane & 7;
    const int a_row  = wm * 64 + ((lm & 1) << 3) + lr8;   // + mi*16
    const int a_choff = (lm >> 1);
    const int b_row  = wn * 64 + ((lm >> 1) << 3) + lr8;  // + nj*16
    const int b_choff = (lm & 1);

    const int iters = K >> 6;

    // prologue: fill 2 of 3 stages
    load_stage(sb, A, B, m0, n0, 0, K, t);
    cp_commit();
    if (iters > 1) { load_stage(sb + STAGE, A, B, m0, n0, 64, K, t); cp_commit(); }

    for (int kt = 0; kt < iters; kt++) {
        if (kt + 1 < iters) cp_wait1();
        else cp_wait0();
        __syncthreads();
        if (kt + 2 < iters) {
            load_stage(sb + (uint32_t)((kt + 2) % 3) * STAGE, A, B, m0, n0, (kt + 2) << 6, K, t);
            cp_commit();
        }

        const uint32_t ss = sb + (uint32_t)(kt % 3) * STAGE;
#pragma unroll
        for (int kk = 0; kk < 4; kk++) {
            uint32_t Af[4][4], Bf[4][4];
            const int chA = 2 * kk + a_choff;
            const int chB = 2 * kk + b_choff;
#pragma unroll
            for (int mi = 0; mi < 4; mi++) {
                int row = a_row + mi * 16;
                uint32_t ad = ss + (row << 7) + (((chA ^ (row & 7))) << 4);
                ldsm4(Af[mi][0], Af[mi][1], Af[mi][2], Af[mi][3], ad);
            }
#pragma unroll
            for (int nj = 0; nj < 4; nj++) {
                int row = b_row + nj * 16;
                uint32_t ad = ss + 16384 + (row << 7) + (((chB ^ (row & 7))) << 4);
                ldsm4(Bf[nj][0], Bf[nj][1], Bf[nj][2], Bf[nj][3], ad);
            }
#pragma unroll
            for (int mi = 0; mi < 4; mi++) {
#pragma unroll
                for (int nj = 0; nj < 4; nj++) {
                    mma16816(acc[mi][nj * 2],     Af[mi], Bf[nj][0], Bf[nj][1]);
                    mma16816(acc[mi][nj * 2 + 1], Af[mi], Bf[nj][2], Bf[nj][3]);
                }
            }
        }
    }

    // epilogue: direct stores from accumulators
    const float scale = scale_ptr ? expf(scale_ptr[0]) : 1.0f;
    const int lr = lane >> 2, lc = (lane & 3) * 2;
#pragma unroll
    for (int mi = 0; mi < 4; mi++) {
#pragma unroll
        for (int nj = 0; nj < 4; nj++) {
#pragma unroll
            for (int h = 0; h < 2; h++) {
                int col = n0 + wn * 64 + nj * 16 + h * 8 + lc;
                float bx = 0.f, by = 0.f;
                if (bias) { float2 bb = *(const float2*)(bias + col); bx = bb.x; by = bb.y; }
#pragma unroll
                for (int rh = 0; rh < 2; rh++) {
                    int row = m0 + wm * 64 + mi * 16 + rh * 8 + lr;
                    float v0 = acc[mi][nj * 2 + h][rh * 2 + 0] + bx;
                    float v1 = acc[mi][nj * 2 + h][rh * 2 + 1] + by;
                    if (act) { v0 = gelu_f(v0); v1 = gelu_f(v1); }
                    v0 *= scale; v1 *= scale;
                    size_t idx = (size_t)row * ldc + col + coff;
                    if (Cf) *(float2*)(Cf + idx) = make_float2(v0, v1);
                    if (Ch) *(__half2*)(Ch + idx) = __floats2half2_rn(v0, v1);
                }
            }
        }
    }
}

// ---------------- fused router softmax + ds sigmoid + expert mix -------------
// hid row: [expert 4096 | dsh 1024 | rth 256], fp16. One block per batch row.
__global__ void router_fuse(const fp16* __restrict__ hid,
                            const float* __restrict__ rtW2,
                            const float* __restrict__ rtb2,
                            const float* __restrict__ dsW2,
                            const float* __restrict__ dsb2,
                            fp16* __restrict__ fusedh,
                            float* __restrict__ ds_buf,
                            float* __restrict__ out_ds,
                            float* __restrict__ out_probs)
{
    int b = blockIdx.x;
    int t = threadIdx.x;           // 256
    int lane = t & 31, w = t >> 5; // 8 warps
    const fp16* row = hid + (size_t)b * NH;

    __shared__ float sl[4], dsp[4], sprob[4], sds;

    if (w < 4) {
        // router logits: warp w -> expert w, dot over rth (256)
        const fp16* x = row + NE * HD + HD;
        const float* wr = rtW2 + (size_t)w * 256;
        float s = 0.f;
        for (int i = lane; i < 256; i += 32) s += __half2float(x[i]) * wr[i];
#pragma unroll
        for (int o = 16; o; o >>= 1) s += __shfl_xor_sync(0xffffffffu, s, o);
        if (lane == 0) sl[w] = s + rtb2[w];
    } else {
        // ds partial dot: warp w-4 handles dsh[256*(w-4) : 256*(w-3)]
        int seg = w - 4;
        const fp16* xr = row + NE * HD;
        float s = 0.f;
        for (int i = seg * 256 + lane; i < (seg + 1) * 256; i += 32)
            s += __half2float(xr[i]) * dsW2[i];
#pragma unroll
        for (int o = 16; o; o >>= 1) s += __shfl_xor_sync(0xffffffffu, s, o);
        if (lane == 0) dsp[seg] = s;
    }
    __syncthreads();

    if (t == 0) {
        float m = fmaxf(fmaxf(sl[0], sl[1]), fmaxf(sl[2], sl[3]));
        float e[4]; float sum = 0.f;
#pragma unroll
        for (int i = 0; i < 4; i++) { e[i] = expf(sl[i] - m); sum += e[i]; }
        float inv = 1.f / sum;
#pragma unroll
        for (int i = 0; i < 4; i++) {
            float p = e[i] * inv;
            sprob[i] = p;
            out_probs[(size_t)b * 4 + i] = p;
        }
    }
    if (t == 32) {
        float d = 1.f / (1.f + expf(-(dsp[0] + dsp[1] + dsp[2] + dsp[3] + dsb2[0])));
        sds = d;
        ds_buf[b] = d;
        out_ds[b] = d;
    }
    __syncthreads();

    float p0 = sprob[0], p1 = sprob[1], p2 = sprob[2], p3 = sprob[3];
    (void)sds;
    for (int h = t; h < HD; h += 256) {
        float v = p0 * __half2float(row[h])          + p1 * __half2float(row[HD + h])
                + p2 * __half2float(row[2 * HD + h]) + p3 * __half2float(row[3 * HD + h]);
        fusedh[(size_t)b * HD + h] = __float2half_rn(v);
    }
}

// ---------------- mix + L2 normalize, emit fp16 (res is fp16 now) ------------
__global__ void norm_kernel(const fp16* __restrict__ res,
                            const float* __restrict__ text,
                            const float* __restrict__ img,
                            const float* __restrict__ ds_buf,
                            const float* __restrict__ target,
                            fp16* __restrict__ predh,
                            fp16* __restrict__ tgth)
{
    int r = blockIdx.x;
    int t = threadIdx.x;  // 256, row length 768 = 3*256
    float o[3];
    fp16* dh;
    size_t base;
    if (r < B_SZ) {
        float d = ds_buf[r];
        base = (size_t)r * FD;
#pragma unroll
        for (int i = 0; i < 3; i++) {
            int j = t + i * 256;
            o[i] = d * text[base + j] + (1.0f - d) * img[base + j]
                 + __half2float(res[base + j]);
        }
        dh = predh;
    } else {
        base = (size_t)(r - B_SZ) * FD;
#pragma unroll
        for (int i = 0; i < 3; i++) o[i] = target[base + t + i * 256];
        dh = tgth;
    }
    float s = o[0] * o[0] + o[1] * o[1] + o[2] * o[2];
    __shared__ float red[256];
    red[t] = s;
    __syncthreads();
    for (int off = 128; off; off >>= 1) {
        if (t < off) red[t] += red[t + off];
        __syncthreads();
    }
    __shared__ float inv_s;
    if (t == 0) inv_s = 1.0f / fmaxf(sqrtf(red[0]), 1e-12f);
    __syncthreads();
    float inv = inv_s;
#pragma unroll
    for (int i = 0; i < 3; i++)
        dh[base + t + i * 256] = __float2half_rn(o[i] * inv);
}

// ---------------- launch -----------------------------------------------------
#define SYM(var, sym) cudaGetSymbolAddress((void**)&var, sym)

extern "C" void kernel_launch(void* const* d_in, const int* in_sizes, int n_in,
                              void* d_out, int out_size)
{
    const float* img  = (const float*)d_in[0];
    const float* txt  = (const float*)d_in[1];
    const float* tgt  = (const float*)d_in[2];
    const float* Wt   = (const float*)d_in[3];
    const float* bt   = (const float*)d_in[4];
    const float* Wi   = (const float*)d_in[5];
    const float* bi   = (const float*)d_in[6];
    const float* dsW1 = (const float*)d_in[7];
    const float* dsb1 = (const float*)d_in[8];
    const float* dsW2 = (const float*)d_in[9];
    const float* dsb2 = (const float*)d_in[10];
    const float* expW = (const float*)d_in[11];
    const float* expb = (const float*)d_in[12];
    const float* rtW1 = (const float*)d_in[13];
    const float* rtb1 = (const float*)d_in[14];
    const float* rtW2 = (const float*)d_in[15];
    const float* rtb2 = (const float*)d_in[16];
    const float* outW = (const float*)d_in[17];
    const float* outb = (const float*)d_in[18];
    const float* lsc  = (const float*)d_in[19];

    float *ds, *bigB;
    fp16 *hid, *resh;
    SYM(ds, g_ds); SYM(hid, g_hid); SYM(bigB, g_bigB); SYM(resh, g_res);

    fp16 *txh, *imh, *cbh, *fuh, *prh, *tgh;
    fp16 *wth, *wih, *bigW, *owh;
    SYM(txh, g_txt_h); SYM(imh, g_img_h);
    SYM(cbh, g_comb_h); SYM(fuh, g_fused_h);
    SYM(prh, g_pred_h); SYM(tgh, g_tgt_h);
    SYM(wth, g_Wt_h); SYM(wih, g_Wi_h); SYM(bigW, g_bigW); SYM(owh, g_outW_h);

    float* out_logits = (float*)d_out;
    float* out_ds     = out_logits + (size_t)B_SZ * T_SZ;
    float* out_probs  = out_ds + B_SZ;

    cudaFuncSetAttribute(gemm_tc, cudaFuncAttributeMaxDynamicSharedMemorySize, SMEM_GEMM);

    // (1) all casts + bias concat in one launch (8 elems/thread)
    megacast<<<NB_TOTAL, 256>>>(txt, img, Wt, Wi, expW, dsW1, rtW1, outW,
                                expb, dsb1, rtb1,
                                txh, imh, wth, wih, bigW, owh, bigB);

    dim3 blk(128);
    // (2) both projections in ONE launch (z=0: txt->cols 0:512, z=1: img->cols 512:1024)
    gemm_tc<<<dim3(PD / 128, B_SZ / 128, 2), blk, SMEM_GEMM>>>(
        txh, wth, bt, nullptr, cbh, FD, CB, 1, nullptr, imh, wih, bi, PD);

    // (3) fused hidden GEMM: [B, 5376] = gelu(comb @ [expW|dsW1|rtW1]^T + bias)
    gemm_tc<<<dim3(NH / 128, B_SZ / 128, 1), blk, SMEM_GEMM>>>(
        cbh, bigW, bigB, nullptr, hid, CB, NH, 1, nullptr, nullptr, nullptr, nullptr, 0);

    // (4) router softmax + ds sigmoid + expert mix, one launch
    router_fuse<<<B_SZ, 256>>>(hid, rtW2, rtb2, dsW2, dsb2, fuh, ds, out_ds, out_probs);

    // (5) residual [B, 768] -> fp16
    gemm_tc<<<dim3(FD / 128, B_SZ / 128, 1), blk, SMEM_GEMM>>>(
        fuh, owh, outb, nullptr, resh, HD, FD, 0, nullptr, nullptr, nullptr, nullptr, 0);

    // (6) mix + normalize -> pred/tgt fp16
    norm_kernel<<<B_SZ + T_SZ, 256>>>(resh, txt, img, ds, tgt, prh, tgh);

    // (7) logits = exp(logit_scale) * pred @ tgt^T   [8192, 8192] f32
    gemm_tc<<<dim3(T_SZ / 128, B_SZ / 128, 1), blk, SMEM_GEMM>>>(
        prh, tgh, nullptr, out_logits, nullptr, FD, T_SZ, 0, lsc, nullptr, nullptr, nullptr, 0);
}

// round 16
// speedup vs baseline: 8.3011x; 1.0413x over previous
#include <cuda_runtime.h>
#include <cuda_fp16.h>
#include <math.h>
#include <stdint.h>

#define B_SZ 8192
#define T_SZ 8192
#define FD 768
#define PD 512
#define HD 1024
#define NE 4
#define CB 1024   // 2*P
#define NH 5376   // fused hidden: 4096 expert | 1024 ds | 256 router

typedef __half fp16;

// ---------------- scratch (device globals; no allocation allowed) ----------
__device__ float g_ds[B_SZ];
__device__ fp16  g_res[(size_t)B_SZ * FD];
__device__ fp16  g_hid[(size_t)B_SZ * NH];

__device__ __align__(256) fp16 g_txt_h[(size_t)B_SZ * FD];
__device__ __align__(256) fp16 g_img_h[(size_t)B_SZ * FD];
__device__ __align__(256) fp16 g_comb_h[(size_t)B_SZ * CB];
__device__ __align__(256) fp16 g_fused_h[(size_t)B_SZ * HD];
__device__ __align__(256) fp16 g_pred_h[(size_t)B_SZ * FD];
__device__ __align__(256) fp16 g_tgt_h[(size_t)T_SZ * FD];
__device__ __align__(256) fp16 g_Wt_h[(size_t)PD * FD];
__device__ __align__(256) fp16 g_Wi_h[(size_t)PD * FD];
__device__ __align__(256) fp16 g_bigW[(size_t)NH * CB];   // [expW | dsW1 | rtW1]
__device__ __align__(256) float g_bigB[NH];
__device__ __align__(256) fp16 g_outW_h[(size_t)FD * HD];

// ---------------- helpers ---------------------------------------------------
__device__ __forceinline__ float gelu_f(float x) {
    return 0.5f * x * (1.0f + erff(x * 0.70710678118654752440f));
}

__device__ __forceinline__ uint32_t smem_u32(const void* p) {
    uint32_t a;
    asm("{ .reg .u64 t; cvta.to.shared.u64 t, %1; cvt.u32.u64 %0, t; }" : "=r"(a) : "l"(p));
    return a;
}

__device__ __forceinline__ void cpasync16(uint32_t dst, const void* src) {
    asm volatile("cp.async.cg.shared.global [%0], [%1], 16;" :: "r"(dst), "l"(src));
}
__device__ __forceinline__ void cp_commit() {
    asm volatile("cp.async.commit_group;" ::: "memory");
}
__device__ __forceinline__ void cp_wait1() {
    asm volatile("cp.async.wait_group 1;" ::: "memory");
}
__device__ __forceinline__ void cp_wait0() {
    asm volatile("cp.async.wait_group 0;" ::: "memory");
}

__device__ __forceinline__ void ldsm4(uint32_t& r0, uint32_t& r1, uint32_t& r2, uint32_t& r3,
                                      uint32_t a) {
    asm volatile("ldmatrix.sync.aligned.m8n8.x4.shared.b16 {%0,%1,%2,%3}, [%4];"
                 : "=r"(r0), "=r"(r1), "=r"(r2), "=r"(r3) : "r"(a));
}

__device__ __forceinline__ void mma16816(float* c, const uint32_t* a, uint32_t b0, uint32_t b1) {
    asm volatile(
        "mma.sync.aligned.m16n8k16.row.col.f32.f16.f16.f32 "
        "{%0,%1,%2,%3}, {%4,%5,%6,%7}, {%8,%9}, {%0,%1,%2,%3};"
        : "+f"(c[0]), "+f"(c[1]), "+f"(c[2]), "+f"(c[3])
        : "r"(a[0]), "r"(a[1]), "r"(a[2]), "r"(a[3]), "r"(b0), "r"(b1));
}

// half2 pair -> floats
__device__ __forceinline__ float2 h2f2(uint32_t h) {
    __half2 v = *(__half2*)&h;
    return __half22float2(v);
}

// ---------------- megacast: all f32->fp16 casts + bias concat, 2048 elem/CTA -
#define NB_TXT  3072
#define NB_IMG  3072
#define NB_WT   192
#define NB_WI   192
#define NB_EXPW 2048
#define NB_DSW  512
#define NB_RTW  128
#define NB_OUTW 384
#define NB_BIAS 3
#define NB_TOTAL (NB_TXT + NB_IMG + NB_WT + NB_WI + NB_EXPW + NB_DSW + NB_RTW + NB_OUTW + NB_BIAS)

__device__ __forceinline__ uint32_t pack2(float a, float b) {
    __half2 h = __floats2half2_rn(a, b);
    return *(uint32_t*)&h;
}

__device__ __forceinline__ void cast8(const float* __restrict__ x, fp16* __restrict__ h,
                                      size_t i) {
    float4 v0 = *(const float4*)(x + i);
    float4 v1 = *(const float4*)(x + i + 4);
    uint4 o;
    o.x = pack2(v0.x, v0.y); o.y = pack2(v0.z, v0.w);
    o.z = pack2(v1.x, v1.y); o.w = pack2(v1.z, v1.w);
    *(uint4*)(h + i) = o;
}

__global__ void megacast(const float* __restrict__ txt,  const float* __restrict__ img,
                         const float* __restrict__ Wt,   const float* __restrict__ Wi,
                         const float* __restrict__ expW, const float* __restrict__ dsW1,
                         const float* __restrict__ rtW1, const float* __restrict__ outW,
                         const float* __restrict__ expb, const float* __restrict__ dsb1,
                         const float* __restrict__ rtb1,
                         fp16* __restrict__ txh,  fp16* __restrict__ imh,
                         fp16* __restrict__ wth,  fp16* __restrict__ wih,
                         fp16* __restrict__ bigW, fp16* __restrict__ owh,
                         float* __restrict__ bigB)
{
    int b = blockIdx.x;
    if (b < NB_TXT) { cast8(txt, txh, ((size_t)b * 256 + threadIdx.x) * 8); return; }
    b -= NB_TXT;
    if (b < NB_IMG) { cast8(img, imh, ((size_t)b * 256 + threadIdx.x) * 8); return; }
    b -= NB_IMG;
    if (b < NB_WT)  { cast8(Wt, wth, ((size_t)b * 256 + threadIdx.x) * 8); return; }
    b -= NB_WT;
    if (b < NB_WI)  { cast8(Wi, wih, ((size_t)b * 256 + threadIdx.x) * 8); return; }
    b -= NB_WI;
    if (b < NB_EXPW) { cast8(expW, bigW, ((size_t)b * 256 + threadIdx.x) * 8); return; }
    b -= NB_EXPW;
    if (b < NB_DSW) {
        cast8(dsW1, bigW + (size_t)NE * HD * CB, ((size_t)b * 256 + threadIdx.x) * 8); return;
    }
    b -= NB_DSW;
    if (b < NB_RTW) {
        cast8(rtW1, bigW + (size_t)(NE * HD + HD) * CB, ((size_t)b * 256 + threadIdx.x) * 8); return;
    }
    b -= NB_RTW;
    if (b < NB_OUTW) { cast8(outW, owh, ((size_t)b * 256 + threadIdx.x) * 8); return; }
    b -= NB_OUTW;
    {   // bias concat: [expb 4096 | dsb1 1024 | rtb1 256] f32
        int i = b * 2048 + threadIdx.x * 8;
#pragma unroll
        for (int q = 0; q < 8; q++) {
            int j = i + q;
            if (j < NH) {
                float v;
                if (j < NE * HD)           v = expb[j];
                else if (j < NE * HD + HD) v = dsb1[j - NE * HD];
                else                       v = rtb1[j - NE * HD - HD];
                bigB[j] = v;
            }
        }
    }
}

// ---------------- fp16 HMMA GEMM ---------------------------------------------
// CTA tile 128x128, K-step 64, 4 warps (2x2, 64x64 warp tiles), 3-stage
// cp.async, single __syncthreads per k-iter, 2 CTAs/SM.
#define STAGE 32768u
#define SMEM_GEMM (3 * STAGE)

__device__ __forceinline__ void load_stage(
    uint32_t sb,
    const fp16* __restrict__ A, const fp16* __restrict__ B,
    int m0, int n0, int k0, int K, int t)
{
#pragma unroll
    for (int i = 0; i < 8; i++) {
        int id = t + (i << 7);
        int row = id >> 3, ch = id & 7;
        uint32_t off = (uint32_t)(row << 7) + (uint32_t)((ch ^ (row & 7)) << 4);
        cpasync16(sb + off, A + (size_t)(m0 + row) * K + k0 + (ch << 3));
    }
#pragma unroll
    for (int i = 0; i < 8; i++) {
        int id = t + (i << 7);
        int row = id >> 3, ch = id & 7;
        uint32_t off = (uint32_t)(row << 7) + (uint32_t)((ch ^ (row & 7)) << 4);
        cpasync16(sb + 16384 + off, B + (size_t)(n0 + row) * K + k0 + (ch << 3));
    }
}

__global__ void __launch_bounds__(128, 2)
gemm_tc(const fp16* __restrict__ A, const fp16* __restrict__ B,
        const float* __restrict__ bias,
        float* __restrict__ Cf, fp16* __restrict__ Ch,
        int K, int ldc, int act, const float* __restrict__ scale_ptr,
        const fp16* __restrict__ A2, const fp16* __restrict__ B2,
        const float* __restrict__ bias2, int colOff2)
{
    extern __shared__ __align__(128) char smem[];
    const uint32_t sb = smem_u32(smem);
    const int t = threadIdx.x;
    const int lane = t & 31, wid = t >> 5;
    const int wm = wid >> 1, wn = wid & 1;
    const int m0 = blockIdx.y * 128;
    const int n0 = blockIdx.x * 128;
    int coff = 0;
    if (blockIdx.z) { A = A2; B = B2; bias = bias2; coff = colOff2; }

    float acc[4][8][4];
#pragma unroll
    for (int i = 0; i < 4; i++)
#pragma unroll
        for (int j = 0; j < 8; j++)
#pragma unroll
            for (int q = 0; q < 4; q++) acc[i][j][q] = 0.f;

    const int lm = lane >> 3, lr8 = lane & 7;
    const int a_row  = wm * 64 + ((lm & 1) << 3) + lr8;
    const int a_choff = (lm >> 1);
    const int b_row  = wn * 64 + ((lm >> 1) << 3) + lr8;
    const int b_choff = (lm & 1);

    const int iters = K >> 6;

    load_stage(sb, A, B, m0, n0, 0, K, t);
    cp_commit();
    if (iters > 1) { load_stage(sb + STAGE, A, B, m0, n0, 64, K, t); cp_commit(); }

    for (int kt = 0; kt < iters; kt++) {
        if (kt + 1 < iters) cp_wait1();
        else cp_wait0();
        __syncthreads();
        if (kt + 2 < iters) {
            load_stage(sb + (uint32_t)((kt + 2) % 3) * STAGE, A, B, m0, n0, (kt + 2) << 6, K, t);
            cp_commit();
        }

        const uint32_t ss = sb + (uint32_t)(kt % 3) * STAGE;
#pragma unroll
        for (int kk = 0; kk < 4; kk++) {
            uint32_t Af[4][4], Bf[4][4];
            const int chA = 2 * kk + a_choff;
            const int chB = 2 * kk + b_choff;
#pragma unroll
            for (int mi = 0; mi < 4; mi++) {
                int row = a_row + mi * 16;
                uint32_t ad = ss + (row << 7) + (((chA ^ (row & 7))) << 4);
                ldsm4(Af[mi][0], Af[mi][1], Af[mi][2], Af[mi][3], ad);
            }
#pragma unroll
            for (int nj = 0; nj < 4; nj++) {
                int row = b_row + nj * 16;
                uint32_t ad = ss + 16384 + (row << 7) + (((chB ^ (row & 7))) << 4);
                ldsm4(Bf[nj][0], Bf[nj][1], Bf[nj][2], Bf[nj][3], ad);
            }
#pragma unroll
            for (int mi = 0; mi < 4; mi++) {
#pragma unroll
                for (int nj = 0; nj < 4; nj++) {
                    mma16816(acc[mi][nj * 2],     Af[mi], Bf[nj][0], Bf[nj][1]);
                    mma16816(acc[mi][nj * 2 + 1], Af[mi], Bf[nj][2], Bf[nj][3]);
                }
            }
        }
    }

    const float scale = scale_ptr ? expf(scale_ptr[0]) : 1.0f;
    const int lr = lane >> 2, lc = (lane & 3) * 2;
#pragma unroll
    for (int mi = 0; mi < 4; mi++) {
#pragma unroll
        for (int nj = 0; nj < 4; nj++) {
#pragma unroll
            for (int h = 0; h < 2; h++) {
                int col = n0 + wn * 64 + nj * 16 + h * 8 + lc;
                float bx = 0.f, by = 0.f;
                if (bias) { float2 bb = *(const float2*)(bias + col); bx = bb.x; by = bb.y; }
#pragma unroll
                for (int rh = 0; rh < 2; rh++) {
                    int row = m0 + wm * 64 + mi * 16 + rh * 8 + lr;
                    float v0 = acc[mi][nj * 2 + h][rh * 2 + 0] + bx;
                    float v1 = acc[mi][nj * 2 + h][rh * 2 + 1] + by;
                    if (act) { v0 = gelu_f(v0); v1 = gelu_f(v1); }
                    v0 *= scale; v1 *= scale;
                    size_t idx = (size_t)row * ldc + col + coff;
                    if (Cf) *(float2*)(Cf + idx) = make_float2(v0, v1);
                    if (Ch) *(__half2*)(Ch + idx) = __floats2half2_rn(v0, v1);
                }
            }
        }
    }
}

// ---------------- fused router softmax + ds sigmoid + expert mix (vectorized) -
// hid row: [expert 4096 | dsh 1024 | rth 256], fp16. One block per batch row.
__global__ void router_fuse(const fp16* __restrict__ hid,
                            const float* __restrict__ rtW2,
                            const float* __restrict__ rtb2,
                            const float* __restrict__ dsW2,
                            const float* __restrict__ dsb2,
                            fp16* __restrict__ fusedh,
                            float* __restrict__ ds_buf,
                            float* __restrict__ out_ds,
                            float* __restrict__ out_probs)
{
    int b = blockIdx.x;
    int t = threadIdx.x;           // 256
    int lane = t & 31, w = t >> 5; // 8 warps
    const fp16* row = hid + (size_t)b * NH;

    __shared__ float sl[4], dsp[4], sprob[4];

    if (w < 4) {
        // router logits: warp w -> expert w, dot over rth (256) via half2
        const fp16* x = row + NE * HD + HD;
        const float* wr = rtW2 + (size_t)w * 256;
        float s = 0.f;
#pragma unroll
        for (int i = lane; i < 128; i += 32) {          // 128 half2 pairs
            float2 xv = h2f2(*(const uint32_t*)(x + 2 * i));
            float2 wv = *(const float2*)(wr + 2 * i);
            s += xv.x * wv.x + xv.y * wv.y;
        }
#pragma unroll
        for (int o = 16; o; o >>= 1) s += __shfl_xor_sync(0xffffffffu, s, o);
        if (lane == 0) sl[w] = s + rtb2[w];
    } else {
        // ds partial dot: warp w-4 handles dsh[256*(w-4) : 256*(w-3)] via half2
        int seg = w - 4;
        const fp16* xr = row + NE * HD + seg * 256;
        const float* wd = dsW2 + seg * 256;
        float s = 0.f;
#pragma unroll
        for (int i = lane; i < 128; i += 32) {
            float2 xv = h2f2(*(const uint32_t*)(xr + 2 * i));
            float2 wv = *(const float2*)(wd + 2 * i);
            s += xv.x * wv.x + xv.y * wv.y;
        }
#pragma unroll
        for (int o = 16; o; o >>= 1) s += __shfl_xor_sync(0xffffffffu, s, o);
        if (lane == 0) dsp[seg] = s;
    }
    __syncthreads();

    if (t == 0) {
        float m = fmaxf(fmaxf(sl[0], sl[1]), fmaxf(sl[2], sl[3]));
        float e[4]; float sum = 0.f;
#pragma unroll
        for (int i = 0; i < 4; i++) { e[i] = expf(sl[i] - m); sum += e[i]; }
        float inv = 1.f / sum;
        float4 p = make_float4(e[0] * inv, e[1] * inv, e[2] * inv, e[3] * inv);
        sprob[0] = p.x; sprob[1] = p.y; sprob[2] = p.z; sprob[3] = p.w;
        *(float4*)(out_probs + (size_t)b * 4) = p;
    }
    if (t == 32) {
        float d = 1.f / (1.f + expf(-(dsp[0] + dsp[1] + dsp[2] + dsp[3] + dsb2[0])));
        ds_buf[b] = d;
        out_ds[b] = d;
    }
    __syncthreads();

    float p0 = sprob[0], p1 = sprob[1], p2 = sprob[2], p3 = sprob[3];
    // expert mix: thread t handles 4 consecutive h (256*4 = 1024)
    {
        int h = t * 4;
        uint2 e0 = *(const uint2*)(row + h);
        uint2 e1 = *(const uint2*)(row + HD + h);
        uint2 e2 = *(const uint2*)(row + 2 * HD + h);
        uint2 e3 = *(const uint2*)(row + 3 * HD + h);
        float2 a0 = h2f2(e0.x), b0 = h2f2(e0.y);
        float2 a1 = h2f2(e1.x), b1 = h2f2(e1.y);
        float2 a2 = h2f2(e2.x), b2 = h2f2(e2.y);
        float2 a3 = h2f2(e3.x), b3 = h2f2(e3.y);
        float v0 = p0 * a0.x + p1 * a1.x + p2 * a2.x + p3 * a3.x;
        float v1 = p0 * a0.y + p1 * a1.y + p2 * a2.y + p3 * a3.y;
        float v2 = p0 * b0.x + p1 * b1.x + p2 * b2.x + p3 * b3.x;
        float v3 = p0 * b0.y + p1 * b1.y + p2 * b2.y + p3 * b3.y;
        uint2 o;
        o.x = pack2(v0, v1);
        o.y = pack2(v2, v3);
        *(uint2*)(fusedh + (size_t)b * HD + h) = o;
    }
}

// ---------------- mix + L2 normalize, vectorized (float4 / 4xfp16) -----------
__global__ void norm_kernel(const fp16* __restrict__ res,
                            const float* __restrict__ text,
                            const float* __restrict__ img,
                            const float* __restrict__ ds_buf,
                            const float* __restrict__ target,
                            fp16* __restrict__ predh,
                            fp16* __restrict__ tgth)
{
    int r = blockIdx.x;
    int t = threadIdx.x;  // 256; threads 0..191 active (192*4 = 768)
    float o[4] = {0.f, 0.f, 0.f, 0.f};
    fp16* dh;
    size_t base;
    bool active = t < 192;
    int j = t * 4;
    if (r < B_SZ) {
        float d = ds_buf[r];
        base = (size_t)r * FD;
        if (active) {
            float4 tx = *(const float4*)(text + base + j);
            float4 im = *(const float4*)(img + base + j);
            uint2 rs = *(const uint2*)(res + base + j);
            float2 r01 = h2f2(rs.x), r23 = h2f2(rs.y);
            o[0] = d * tx.x + (1.0f - d) * im.x + r01.x;
            o[1] = d * tx.y + (1.0f - d) * im.y + r01.y;
            o[2] = d * tx.z + (1.0f - d) * im.z + r23.x;
            o[3] = d * tx.w + (1.0f - d) * im.w + r23.y;
        }
        dh = predh;
    } else {
        base = (size_t)(r - B_SZ) * FD;
        if (active) {
            float4 tg = *(const float4*)(target + base + j);
            o[0] = tg.x; o[1] = tg.y; o[2] = tg.z; o[3] = tg.w;
        }
        dh = tgth;
    }
    float s = o[0] * o[0] + o[1] * o[1] + o[2] * o[2] + o[3] * o[3];
    __shared__ float red[256];
    red[t] = s;
    __syncthreads();
    for (int off = 128; off; off >>= 1) {
        if (t < off) red[t] += red[t + off];
        __syncthreads();
    }
    __shared__ float inv_s;
    if (t == 0) inv_s = 1.0f / fmaxf(sqrtf(red[0]), 1e-12f);
    __syncthreads();
    float inv = inv_s;
    if (active) {
        uint2 w;
        w.x = pack2(o[0] * inv, o[1] * inv);
        w.y = pack2(o[2] * inv, o[3] * inv);
        *(uint2*)(dh + base + j) = w;
    }
}

// ---------------- launch -----------------------------------------------------
#define SYM(var, sym) cudaGetSymbolAddress((void**)&var, sym)

extern "C" void kernel_launch(void* const* d_in, const int* in_sizes, int n_in,
                              void* d_out, int out_size)
{
    const float* img  = (const float*)d_in[0];
    const float* txt  = (const float*)d_in[1];
    const float* tgt  = (const float*)d_in[2];
    const float* Wt   = (const float*)d_in[3];
    const float* bt   = (const float*)d_in[4];
    const float* Wi   = (const float*)d_in[5];
    const float* bi   = (const float*)d_in[6];
    const float* dsW1 = (const float*)d_in[7];
    const float* dsb1 = (const float*)d_in[8];
    const float* dsW2 = (const float*)d_in[9];
    const float* dsb2 = (const float*)d_in[10];
    const float* expW = (const float*)d_in[11];
    const float* expb = (const float*)d_in[12];
    const float* rtW1 = (const float*)d_in[13];
    const float* rtb1 = (const float*)d_in[14];
    const float* rtW2 = (const float*)d_in[15];
    const float* rtb2 = (const float*)d_in[16];
    const float* outW = (const float*)d_in[17];
    const float* outb = (const float*)d_in[18];
    const float* lsc  = (const float*)d_in[19];

    float *ds, *bigB;
    fp16 *hid, *resh;
    SYM(ds, g_ds); SYM(hid, g_hid); SYM(bigB, g_bigB); SYM(resh, g_res);

    fp16 *txh, *imh, *cbh, *fuh, *prh, *tgh;
    fp16 *wth, *wih, *bigW, *owh;
    SYM(txh, g_txt_h); SYM(imh, g_img_h);
    SYM(cbh, g_comb_h); SYM(fuh, g_fused_h);
    SYM(prh, g_pred_h); SYM(tgh, g_tgt_h);
    SYM(wth, g_Wt_h); SYM(wih, g_Wi_h); SYM(bigW, g_bigW); SYM(owh, g_outW_h);

    float* out_logits = (float*)d_out;
    float* out_ds     = out_logits + (size_t)B_SZ * T_SZ;
    float* out_probs  = out_ds + B_SZ;

    cudaFuncSetAttribute(gemm_tc, cudaFuncAttributeMaxDynamicSharedMemorySize, SMEM_GEMM);

    // (1) all casts + bias concat in one launch
    megacast<<<NB_TOTAL, 256>>>(txt, img, Wt, Wi, expW, dsW1, rtW1, outW,
                                expb, dsb1, rtb1,
                                txh, imh, wth, wih, bigW, owh, bigB);

    dim3 blk(128);
    // (2) both projections in ONE launch
    gemm_tc<<<dim3(PD / 128, B_SZ / 128, 2), blk, SMEM_GEMM>>>(
        txh, wth, bt, nullptr, cbh, FD, CB, 1, nullptr, imh, wih, bi, PD);

    // (3) fused hidden GEMM: [B, 5376]
    gemm_tc<<<dim3(NH / 128, B_SZ / 128, 1), blk, SMEM_GEMM>>>(
        cbh, bigW, bigB, nullptr, hid, CB, NH, 1, nullptr, nullptr, nullptr, nullptr, 0);

    // (4) router softmax + ds sigmoid + expert mix
    router_fuse<<<B_SZ, 256>>>(hid, rtW2, rtb2, dsW2, dsb2, fuh, ds, out_ds, out_probs);

    // (5) residual [B, 768] -> fp16
    gemm_tc<<<dim3(FD / 128, B_SZ / 128, 1), blk, SMEM_GEMM>>>(
        fuh, owh, outb, nullptr, resh, HD, FD, 0, nullptr, nullptr, nullptr, nullptr, 0);

    // (6) mix + normalize -> pred/tgt fp16
    norm_kernel<<<B_SZ + T_SZ, 256>>>(resh, txt, img, ds, tgt, prh, tgh);

    // (7) logits = exp(logit_scale) * pred @ tgt^T   [8192, 8192] f32
    gemm_tc<<<dim3(T_SZ / 128, B_SZ / 128, 1), blk, SMEM_GEMM>>>(
        prh, tgh, nullptr, out_logits, nullptr, FD, T_SZ, 0, lsc, nullptr, nullptr, nullptr, 0);
}